// round 5
// baseline (speedup 1.0000x reference)
#include <cuda_runtime.h>
#include <math.h>

#define NN 50000
#define EE 800000
#define GG 256
#define NLAYERS 4
#define ETOT (EE + NN)

// ---------------- static device scratch (no allocation allowed) ----------------
__device__ float d_h [NN * 64];     // node features (current)
__device__ float d_xp[NN * 64];     // per-head transformed features for current layer
__device__ float d_as[NN * 4];      // attention src logits per head
__device__ float d_ad[NN * 4];      // attention dst logits per head
__device__ int   d_cnt[NN];         // in-degree (incl self loop)
__device__ int   d_rowptr[NN + 1];  // CSR row pointers by dst
__device__ int   d_cursor[NN];      // scatter cursors
__device__ int   d_csrc[ETOT];      // CSR: src index per incoming edge
__device__ float d_bn[128];         // [0:64) sum, [64:128) sumsq
__device__ float d_g [GG * 64];     // pooled graph features

// ---------------- CSR build ----------------
__global__ void init_cnt_kernel() {
    int i = blockIdx.x * blockDim.x + threadIdx.x;
    if (i < NN) d_cnt[i] = 1;   // self loop pre-counted
}

__global__ void hist_kernel(const int* __restrict__ ei) {
    int i = blockIdx.x * blockDim.x + threadIdx.x;
    if (i < EE) atomicAdd(&d_cnt[ei[EE + i]], 1);
}

// single-block exclusive scan over 50000 counters
__global__ void scan_kernel() {
    __shared__ int sh[1024];
    __shared__ int carry_s;
    if (threadIdx.x == 0) carry_s = 0;
    __syncthreads();
    for (int base = 0; base < NN; base += 1024) {
        int i = base + threadIdx.x;
        int v = (i < NN) ? d_cnt[i] : 0;
        sh[threadIdx.x] = v;
        __syncthreads();
        #pragma unroll
        for (int off = 1; off < 1024; off <<= 1) {
            int t = (threadIdx.x >= off) ? sh[threadIdx.x - off] : 0;
            __syncthreads();
            sh[threadIdx.x] += t;
            __syncthreads();
        }
        if (i < NN) d_rowptr[i] = carry_s + sh[threadIdx.x] - v;
        __syncthreads();
        if (threadIdx.x == 0) carry_s += sh[1023];
        __syncthreads();
    }
    if (threadIdx.x == 0) d_rowptr[NN] = carry_s;
}

__global__ void copy_cursor_kernel() {
    int i = blockIdx.x * blockDim.x + threadIdx.x;
    if (i < NN) d_cursor[i] = d_rowptr[i];
}

__global__ void scatter_edges_kernel(const int* __restrict__ ei) {
    int i = blockIdx.x * blockDim.x + threadIdx.x;
    if (i < EE) {
        int dst = ei[EE + i];
        int pos = atomicAdd(&d_cursor[dst], 1);
        d_csrc[pos] = ei[i];
    }
}

__global__ void scatter_loops_kernel() {
    int i = blockIdx.x * blockDim.x + threadIdx.x;
    if (i < NN) {
        int pos = atomicAdd(&d_cursor[i], 1);
        d_csrc[pos] = i;
    }
}

// ---------------- GEMM (X[nrows,K] @ W[K,64] (+bias) -> out[nrows,64]) ----------------
// optionally fuses per-head attention logits: a_s[n,h] = sum_c out[n,h*16+c]*attS[h*16+c]
template<int K, int NB, bool BIAS, bool ATT>
__global__ void gemm_kernel(const float* __restrict__ X, const float* __restrict__ W,
                            const float* __restrict__ bias,
                            const float* __restrict__ attS, const float* __restrict__ attD,
                            float* __restrict__ out,
                            float* __restrict__ asOut, float* __restrict__ adOut,
                            int nrows)
{
    constexpr int U = NB / 4;
    __shared__ float Wsh[K * 64];
    __shared__ float Xsh[NB * K];
    int tid = threadIdx.x;
    for (int i = tid; i < K * 64; i += 256) Wsh[i] = W[i];
    int nb = blockIdx.x * NB;
    for (int i = tid; i < NB * K; i += 256) {
        int r = i / K, k = i - r * K;
        int row = nb + r;
        Xsh[i] = (row < nrows) ? X[row * K + k] : 0.0f;
    }
    __syncthreads();

    int j  = tid & 63;   // output channel
    int r0 = tid >> 6;   // 0..3 (uniform within a warp)
    float acc[U];
    #pragma unroll
    for (int u = 0; u < U; u++) acc[u] = 0.0f;

    #pragma unroll 4
    for (int k = 0; k < K; k++) {
        float w = Wsh[k * 64 + j];
        #pragma unroll
        for (int u = 0; u < U; u++)
            acc[u] = fmaf(Xsh[(r0 + 4 * u) * K + k], w, acc[u]);
    }

    float b  = BIAS ? bias[j] : 0.0f;
    float es = 0.0f, ed = 0.0f;
    if (ATT) { es = attS[j]; ed = attD[j]; }
    int lane = tid & 31;

    #pragma unroll
    for (int u = 0; u < U; u++) {
        int row = nb + r0 + 4 * u;
        float v = acc[u] + b;
        if (row < nrows) out[row * 64 + j] = v;
        if (ATT) {
            float vs = v * es, vd = v * ed;
            #pragma unroll
            for (int off = 8; off; off >>= 1) {
                vs += __shfl_xor_sync(0xffffffffu, vs, off);
                vd += __shfl_xor_sync(0xffffffffu, vd, off);
            }
            if ((lane & 15) == 0 && row < nrows) {
                int head = j >> 4;
                asOut[row * 4 + head] = vs;
                adOut[row * 4 + head] = vd;
            }
        }
    }
}

// ---------------- attention gather: one warp per dst node ----------------
// phase A: per-head max of leaky_relu(a_s[src]+a_d[dst]) over incoming edges
// phase B: softmax-weighted sum of xp[src] into 64 channels (2 per lane)
// epilogue: +gat_b, write h, accumulate BN stats
__device__ __forceinline__ float lrelu(float x) { return x > 0.0f ? x : 0.2f * x; }

__global__ void gather_kernel(const float* __restrict__ gb)
{
    __shared__ float shsum[64], shsq[64];
    if (threadIdx.x < 64) { shsum[threadIdx.x] = 0.0f; shsq[threadIdx.x] = 0.0f; }
    __syncthreads();

    int lane = threadIdx.x & 31;
    int n = blockIdx.x * 4 + (threadIdx.x >> 5);
    if (n < NN) {
        int beg = d_rowptr[n], end = d_rowptr[n + 1];
        float4 ad = *reinterpret_cast<const float4*>(d_ad + n * 4);

        float m0 = -1e30f, m1 = -1e30f, m2 = -1e30f, m3 = -1e30f;
        for (int i = beg + lane; i < end; i += 32) {
            int s = d_csrc[i];
            float4 as = *reinterpret_cast<const float4*>(d_as + s * 4);
            m0 = fmaxf(m0, lrelu(as.x + ad.x));
            m1 = fmaxf(m1, lrelu(as.y + ad.y));
            m2 = fmaxf(m2, lrelu(as.z + ad.z));
            m3 = fmaxf(m3, lrelu(as.w + ad.w));
        }
        #pragma unroll
        for (int off = 16; off; off >>= 1) {
            m0 = fmaxf(m0, __shfl_xor_sync(0xffffffffu, m0, off));
            m1 = fmaxf(m1, __shfl_xor_sync(0xffffffffu, m1, off));
            m2 = fmaxf(m2, __shfl_xor_sync(0xffffffffu, m2, off));
            m3 = fmaxf(m3, __shfl_xor_sync(0xffffffffu, m3, off));
        }

        float acc0 = 0.0f, acc1 = 0.0f;
        float s0 = 0.0f, s1 = 0.0f, s2 = 0.0f, s3 = 0.0f;
        int hsel = (lane >> 4) & 1;
        for (int i = beg; i < end; i++) {
            int s = d_csrc[i];
            float4 as = *reinterpret_cast<const float4*>(d_as + s * 4);
            float p0 = __expf(lrelu(as.x + ad.x) - m0);
            float p1 = __expf(lrelu(as.y + ad.y) - m1);
            float p2 = __expf(lrelu(as.z + ad.z) - m2);
            float p3 = __expf(lrelu(as.w + ad.w) - m3);
            s0 += p0; s1 += p1; s2 += p2; s3 += p3;
            float pa = hsel ? p1 : p0;
            float pb = hsel ? p3 : p2;
            acc0 = fmaf(d_xp[s * 64 + lane],      pa, acc0);
            acc1 = fmaf(d_xp[s * 64 + 32 + lane], pb, acc1);
        }
        float sa = hsel ? s1 : s0;
        float sb = hsel ? s3 : s2;
        float v0 = acc0 / (sa + 1e-16f) + gb[lane];
        float v1 = acc1 / (sb + 1e-16f) + gb[32 + lane];
        d_h[n * 64 + lane]      = v0;
        d_h[n * 64 + 32 + lane] = v1;
        atomicAdd(&shsum[lane],      v0); atomicAdd(&shsq[lane],      v0 * v0);
        atomicAdd(&shsum[32 + lane], v1); atomicAdd(&shsq[32 + lane], v1 * v1);
    }
    __syncthreads();
    if (threadIdx.x < 64) {
        atomicAdd(&d_bn[threadIdx.x],      shsum[threadIdx.x]);
        atomicAdd(&d_bn[64 + threadIdx.x], shsq[threadIdx.x]);
    }
}

__global__ void zero_bn_kernel() {
    if (threadIdx.x < 128) d_bn[threadIdx.x] = 0.0f;
}

__global__ void bn_elu_kernel(const float* __restrict__ gamma, const float* __restrict__ beta)
{
    int idx = blockIdx.x * blockDim.x + threadIdx.x;
    if (idx >= NN * 64) return;
    int j = idx & 63;
    const float invN = 1.0f / (float)NN;
    float mu  = d_bn[j] * invN;
    float var = d_bn[64 + j] * invN - mu * mu;
    float rs  = rsqrtf(var + 1e-5f);
    float v = (d_h[idx] - mu) * rs * gamma[j] + beta[j];
    d_h[idx] = v > 0.0f ? v : expm1f(v);
}

// ---------------- pooling + MLP head ----------------
__global__ void zero_g_kernel() {
    int idx = blockIdx.x * blockDim.x + threadIdx.x;
    if (idx < GG * 64) d_g[idx] = 0.0f;
}

__global__ void pool_kernel(const int* __restrict__ batch) {
    int idx = blockIdx.x * blockDim.x + threadIdx.x;
    if (idx >= NN * 64) return;
    int n = idx >> 6, j = idx & 63;
    atomicAdd(&d_g[batch[n] * 64 + j], d_h[idx]);
}

__global__ void head_kernel(const float* __restrict__ fc1W, const float* __restrict__ fc1b,
                            const float* __restrict__ fc2W, const float* __restrict__ fc2b,
                            float* __restrict__ out)
{
    __shared__ float gv[64];
    __shared__ float partial[2];
    int g = blockIdx.x, j = threadIdx.x;
    gv[j] = d_g[g * 64 + j];
    __syncthreads();
    float acc = fc1b[j];
    #pragma unroll
    for (int k = 0; k < 64; k++) acc = fmaf(gv[k], fc1W[k * 64 + j], acc);
    acc = fmaxf(acc, 0.0f) * fc2W[j];
    #pragma unroll
    for (int off = 16; off; off >>= 1) acc += __shfl_xor_sync(0xffffffffu, acc, off);
    if ((j & 31) == 0) partial[j >> 5] = acc;
    __syncthreads();
    if (j == 0) out[g] = partial[0] + partial[1] + fc2b[0];
}

// ---------------- launch ----------------
extern "C" void kernel_launch(void* const* d_in, const int* in_sizes, int n_in,
                              void* d_out, int out_size)
{
    const float* x     = (const float*)d_in[0];
    const float* embW  = (const float*)d_in[1];
    const float* embB  = (const float*)d_in[2];
    const float* gatW  = (const float*)d_in[3];
    const float* attS  = (const float*)d_in[4];
    const float* attD  = (const float*)d_in[5];
    const float* gatB  = (const float*)d_in[6];
    const float* bnG   = (const float*)d_in[7];
    const float* bnB   = (const float*)d_in[8];
    const float* fc1W  = (const float*)d_in[9];
    const float* fc1b  = (const float*)d_in[10];
    const float* fc2W  = (const float*)d_in[11];
    const float* fc2b  = (const float*)d_in[12];
    const int*   ei    = (const int*)d_in[13];
    const int*   batch = (const int*)d_in[14];
    float* out = (float*)d_out;

    void* p;
    cudaGetSymbolAddress(&p, d_h);  float* h  = (float*)p;
    cudaGetSymbolAddress(&p, d_xp); float* xp = (float*)p;
    cudaGetSymbolAddress(&p, d_as); float* pas = (float*)p;
    cudaGetSymbolAddress(&p, d_ad); float* pad = (float*)p;

    const int TB = 256;
    const int gridN  = (NN + TB - 1) / TB;   // 196
    const int gridE  = (EE + TB - 1) / TB;   // 3125
    const int gridNE = (NN * 64) / TB;       // 12500

    // CSR by dst (rebuilt every call — deterministic)
    init_cnt_kernel<<<gridN, TB>>>();
    hist_kernel<<<gridE, TB>>>(ei);
    scan_kernel<<<1, 1024>>>();
    copy_cursor_kernel<<<gridN, TB>>>();
    scatter_edges_kernel<<<gridE, TB>>>(ei);
    scatter_loops_kernel<<<gridN, TB>>>();

    // node embedding: x[N,128] @ embW + embB -> h
    gemm_kernel<128, 16, true, false><<<(NN + 15) / 16, 256>>>(
        x, embW, embB, nullptr, nullptr, h, nullptr, nullptr, NN);

    for (int l = 0; l < NLAYERS; l++) {
        gemm_kernel<64, 32, false, true><<<(NN + 31) / 32, 256>>>(
            h, gatW + l * 64 * 64, nullptr, attS + l * 64, attD + l * 64,
            xp, pas, pad, NN);
        zero_bn_kernel<<<1, 128>>>();
        gather_kernel<<<(NN + 3) / 4, 128>>>(gatB + l * 64);
        bn_elu_kernel<<<gridNE, TB>>>(bnG + l * 64, bnB + l * 64);
    }

    zero_g_kernel<<<(GG * 64 + TB - 1) / TB, TB>>>();
    pool_kernel<<<gridNE, TB>>>(batch);
    head_kernel<<<GG, 64>>>(fc1W, fc1b, fc2W, fc2b, out);
}

// round 6
// speedup vs baseline: 1.2062x; 1.2062x over previous
#include <cuda_runtime.h>
#include <math.h>

#define NN 50000
#define EE 800000
#define GG 256
#define NLAYERS 4
#define ETOT (EE + NN)
#define SCAN_BLK ((NN + 1023) / 1024)   // 49

// ---------------- static device scratch ----------------
__device__ __align__(16) float d_h [NN * 64];   // node features (pre-BN after gather)
__device__ __align__(16) float d_xp[NN * 64];   // per-head transformed features
__device__ __align__(16) float d_as[NN * 4];
__device__ __align__(16) float d_ad[NN * 4];
__device__ int   d_cnt[NN];          // in-degree histogram (kept zeroed between calls)
__device__ int   d_rowptr[NN + 1];
__device__ int   d_cursor[NN];
__device__ int   d_bsum[SCAN_BLK];
__device__ int   d_csrc[ETOT];
__device__ float d_bn[128];          // [0:64) sum, [64:128) sumsq (kept zeroed between calls)
__device__ float d_bnscale[64];
__device__ float d_bnshift[64];
__device__ float d_g [GG * 64];

__device__ __forceinline__ float lrelu(float x) { return x > 0.0f ? x : 0.2f * x; }
__device__ __forceinline__ float elu(float x)   { return x > 0.0f ? x : expm1f(x); }

// ---------------- CSR build ----------------
__global__ void hist_kernel(const int* __restrict__ ei) {
    int i = blockIdx.x * blockDim.x + threadIdx.x;
    if (i < EE) atomicAdd(&d_cnt[ei[EE + i]], 1);
}

// block-local exclusive scan (1024/block), +1 per node for self loop
__global__ void scanA_kernel() {
    __shared__ int wsum[32];
    int i = blockIdx.x * 1024 + threadIdx.x;
    int lane = threadIdx.x & 31, warp = threadIdx.x >> 5;
    int v = (i < NN) ? d_cnt[i] + 1 : 0;
    int orig = v;
    #pragma unroll
    for (int off = 1; off < 32; off <<= 1) {
        int t = __shfl_up_sync(0xffffffffu, v, off);
        if (lane >= off) v += t;
    }
    if (lane == 31) wsum[warp] = v;
    __syncthreads();
    if (threadIdx.x < 32) {
        int w = wsum[threadIdx.x];
        #pragma unroll
        for (int off = 1; off < 32; off <<= 1) {
            int t = __shfl_up_sync(0xffffffffu, w, off);
            if (lane >= off) w += t;
        }
        wsum[threadIdx.x] = w;
    }
    __syncthreads();
    int prefix = warp ? wsum[warp - 1] : 0;
    int incl = v + prefix;
    if (i < NN) d_rowptr[i] = incl - orig;
    if (threadIdx.x == 1023) d_bsum[blockIdx.x] = incl;
}

__global__ void scanB_kernel() {
    if (threadIdx.x == 0) {
        int acc = 0;
        #pragma unroll
        for (int b = 0; b < SCAN_BLK; b++) { int t = d_bsum[b]; d_bsum[b] = acc; acc += t; }
        d_rowptr[NN] = acc;   // == ETOT
    }
}

__global__ void scanC_kernel() {
    int i = blockIdx.x * blockDim.x + threadIdx.x;
    if (i < NN) {
        int r = d_rowptr[i] + d_bsum[i >> 10];
        d_rowptr[i] = r;
        d_cursor[i] = r;
        d_cnt[i] = 0;   // ready for next call
    }
}

__global__ void scatter_kernel(const int* __restrict__ ei) {
    int i = blockIdx.x * blockDim.x + threadIdx.x;
    if (i < EE) {
        int dst = ei[EE + i];
        int pos = atomicAdd(&d_cursor[dst], 1);
        d_csrc[pos] = ei[i];
    } else if (i < EE + NN) {
        int n = i - EE;
        int pos = atomicAdd(&d_cursor[n], 1);
        d_csrc[pos] = n;
    }
}

// ---------------- GEMM: X[nrows,K] @ W[K,64] (+bias) -> out ----------------
// BNF: applies y = elu(x*scale + shift) to X elements on load (fused BN+ELU of prev layer)
// ATT: fuses per-head attention logits via 16-lane shuffle reduction
template<int K, int NB, bool BIAS, bool ATT, bool BNF>
__global__ void gemm_kernel(const float* __restrict__ X, const float* __restrict__ W,
                            const float* __restrict__ bias,
                            const float* __restrict__ attS, const float* __restrict__ attD,
                            float* __restrict__ out,
                            float* __restrict__ asOut, float* __restrict__ adOut,
                            int nrows)
{
    constexpr int U = NB / 4;
    __shared__ float Wsh[K * 64];
    __shared__ float Xsh[NB * K];
    int tid = threadIdx.x;
    for (int i = tid; i < K * 64; i += 256) Wsh[i] = W[i];
    int nb = blockIdx.x * NB;
    for (int i = tid; i < NB * K; i += 256) {
        int r = i / K, k = i - r * K;
        int row = nb + r;
        float v = (row < nrows) ? X[row * K + k] : 0.0f;
        if (BNF) v = elu(fmaf(v, d_bnscale[k], d_bnshift[k]));
        Xsh[i] = v;
    }
    __syncthreads();

    int j  = tid & 63;
    int r0 = tid >> 6;
    float acc[U];
    #pragma unroll
    for (int u = 0; u < U; u++) acc[u] = 0.0f;

    #pragma unroll 4
    for (int k = 0; k < K; k++) {
        float w = Wsh[k * 64 + j];
        #pragma unroll
        for (int u = 0; u < U; u++)
            acc[u] = fmaf(Xsh[(r0 + 4 * u) * K + k], w, acc[u]);
    }

    float b  = BIAS ? bias[j] : 0.0f;
    float es = 0.0f, ed = 0.0f;
    if (ATT) { es = attS[j]; ed = attD[j]; }
    int lane = tid & 31;

    #pragma unroll
    for (int u = 0; u < U; u++) {
        int row = nb + r0 + 4 * u;
        float v = acc[u] + b;
        if (row < nrows) out[row * 64 + j] = v;
        if (ATT) {
            float vs = v * es, vd = v * ed;
            #pragma unroll
            for (int off = 8; off; off >>= 1) {
                vs += __shfl_xor_sync(0xffffffffu, vs, off);
                vd += __shfl_xor_sync(0xffffffffu, vd, off);
            }
            if ((lane & 15) == 0 && row < nrows) {
                int head = j >> 4;
                asOut[row * 4 + head] = vs;
                adOut[row * 4 + head] = vd;
            }
        }
    }
}

// ---------------- attention gather: one warp per dst node ----------------
// lane handles channels (2*lane, 2*lane+1) — both in head lane>>3.
// Phase B unrolled by 2 edges for MLP. Epilogue: +gat_b, write h, BN stats.
__global__ void gather_kernel(const float* __restrict__ gb)
{
    __shared__ float shsum[64], shsq[64];
    if (threadIdx.x < 64) { shsum[threadIdx.x] = 0.0f; shsq[threadIdx.x] = 0.0f; }
    __syncthreads();

    int lane = threadIdx.x & 31;
    int n = blockIdx.x * 8 + (threadIdx.x >> 5);
    if (n < NN) {
        int beg = d_rowptr[n], end = d_rowptr[n + 1];
        float4 ad = *reinterpret_cast<const float4*>(d_ad + n * 4);

        // phase A: per-head max (warp-strided)
        float m0 = -1e30f, m1 = -1e30f, m2 = -1e30f, m3 = -1e30f;
        for (int i = beg + lane; i < end; i += 32) {
            int s = __ldg(&d_csrc[i]);
            float4 as = *reinterpret_cast<const float4*>(d_as + s * 4);
            m0 = fmaxf(m0, lrelu(as.x + ad.x));
            m1 = fmaxf(m1, lrelu(as.y + ad.y));
            m2 = fmaxf(m2, lrelu(as.z + ad.z));
            m3 = fmaxf(m3, lrelu(as.w + ad.w));
        }
        #pragma unroll
        for (int off = 16; off; off >>= 1) {
            m0 = fmaxf(m0, __shfl_xor_sync(0xffffffffu, m0, off));
            m1 = fmaxf(m1, __shfl_xor_sync(0xffffffffu, m1, off));
            m2 = fmaxf(m2, __shfl_xor_sync(0xffffffffu, m2, off));
            m3 = fmaxf(m3, __shfl_xor_sync(0xffffffffu, m3, off));
        }

        // phase B: softmax-weighted sum, 2 edges in flight
        int hsel = lane >> 3;   // 0..3
        float ax = 0.0f, ay = 0.0f;
        float s0 = 0.0f, s1 = 0.0f, s2 = 0.0f, s3 = 0.0f;
        int i = beg;
        #pragma unroll 2
        for (; i + 2 <= end; i += 2) {
            int sA = __ldg(&d_csrc[i]);
            int sB = __ldg(&d_csrc[i + 1]);
            float4 aA = *reinterpret_cast<const float4*>(d_as + sA * 4);
            float4 aB = *reinterpret_cast<const float4*>(d_as + sB * 4);
            float2 xA = *reinterpret_cast<const float2*>(d_xp + sA * 64 + 2 * lane);
            float2 xB = *reinterpret_cast<const float2*>(d_xp + sB * 64 + 2 * lane);
            float pA0 = __expf(lrelu(aA.x + ad.x) - m0);
            float pA1 = __expf(lrelu(aA.y + ad.y) - m1);
            float pA2 = __expf(lrelu(aA.z + ad.z) - m2);
            float pA3 = __expf(lrelu(aA.w + ad.w) - m3);
            float pB0 = __expf(lrelu(aB.x + ad.x) - m0);
            float pB1 = __expf(lrelu(aB.y + ad.y) - m1);
            float pB2 = __expf(lrelu(aB.z + ad.z) - m2);
            float pB3 = __expf(lrelu(aB.w + ad.w) - m3);
            s0 += pA0 + pB0; s1 += pA1 + pB1; s2 += pA2 + pB2; s3 += pA3 + pB3;
            float phA = hsel == 0 ? pA0 : hsel == 1 ? pA1 : hsel == 2 ? pA2 : pA3;
            float phB = hsel == 0 ? pB0 : hsel == 1 ? pB1 : hsel == 2 ? pB2 : pB3;
            ax = fmaf(xA.x, phA, ax); ay = fmaf(xA.y, phA, ay);
            ax = fmaf(xB.x, phB, ax); ay = fmaf(xB.y, phB, ay);
        }
        if (i < end) {
            int sA = __ldg(&d_csrc[i]);
            float4 aA = *reinterpret_cast<const float4*>(d_as + sA * 4);
            float2 xA = *reinterpret_cast<const float2*>(d_xp + sA * 64 + 2 * lane);
            float pA0 = __expf(lrelu(aA.x + ad.x) - m0);
            float pA1 = __expf(lrelu(aA.y + ad.y) - m1);
            float pA2 = __expf(lrelu(aA.z + ad.z) - m2);
            float pA3 = __expf(lrelu(aA.w + ad.w) - m3);
            s0 += pA0; s1 += pA1; s2 += pA2; s3 += pA3;
            float phA = hsel == 0 ? pA0 : hsel == 1 ? pA1 : hsel == 2 ? pA2 : pA3;
            ax = fmaf(xA.x, phA, ax); ay = fmaf(xA.y, phA, ay);
        }
        float sh_ = hsel == 0 ? s0 : hsel == 1 ? s1 : hsel == 2 ? s2 : s3;
        float inv = 1.0f / (sh_ + 1e-16f);
        float v0 = ax * inv + gb[2 * lane];
        float v1 = ay * inv + gb[2 * lane + 1];
        *reinterpret_cast<float2*>(d_h + n * 64 + 2 * lane) = make_float2(v0, v1);
        atomicAdd(&shsum[2 * lane],     v0); atomicAdd(&shsq[2 * lane],     v0 * v0);
        atomicAdd(&shsum[2 * lane + 1], v1); atomicAdd(&shsq[2 * lane + 1], v1 * v1);
    }
    __syncthreads();
    if (threadIdx.x < 64) {
        atomicAdd(&d_bn[threadIdx.x],      shsum[threadIdx.x]);
        atomicAdd(&d_bn[64 + threadIdx.x], shsq[threadIdx.x]);
    }
}

// fold BN stats into per-channel scale/shift; re-zero d_bn for next layer/call
__global__ void bnfin_kernel(const float* __restrict__ gamma, const float* __restrict__ beta)
{
    int j = threadIdx.x;
    if (j < 64) {
        const float invN = 1.0f / (float)NN;
        float mu  = d_bn[j] * invN;
        float var = d_bn[64 + j] * invN - mu * mu;
        float sc  = rsqrtf(var + 1e-5f) * gamma[j];
        d_bnscale[j] = sc;
        d_bnshift[j] = beta[j] - mu * sc;
        d_bn[j] = 0.0f; d_bn[64 + j] = 0.0f;
    }
}

// ---------------- pooling (applies last layer's BN+ELU) + MLP head ----------------
__global__ void zero_g_kernel() {
    int idx = blockIdx.x * blockDim.x + threadIdx.x;
    if (idx < GG * 64) d_g[idx] = 0.0f;
}

// thread = (16-node chunk, channel); batch is sorted -> run-length reduce before atomics
__global__ void pool_kernel(const int* __restrict__ batch) {
    int t = blockIdx.x * blockDim.x + threadIdx.x;
    int j = t & 63, chunk = t >> 6;
    int n0 = chunk * 16;
    if (n0 >= NN) return;
    int nend = n0 + 16; if (nend > NN) nend = NN;
    float sc = d_bnscale[j], sh = d_bnshift[j];
    float acc = 0.0f;
    int curb = batch[n0];
    for (int n = n0; n < nend; n++) {
        float v = elu(fmaf(d_h[n * 64 + j], sc, sh));
        int b = batch[n];
        if (b != curb) { atomicAdd(&d_g[curb * 64 + j], acc); acc = 0.0f; curb = b; }
        acc += v;
    }
    atomicAdd(&d_g[curb * 64 + j], acc);
}

__global__ void head_kernel(const float* __restrict__ fc1W, const float* __restrict__ fc1b,
                            const float* __restrict__ fc2W, const float* __restrict__ fc2b,
                            float* __restrict__ out)
{
    __shared__ float gv[64];
    __shared__ float partial[2];
    int g = blockIdx.x, j = threadIdx.x;
    gv[j] = d_g[g * 64 + j];
    __syncthreads();
    float acc = fc1b[j];
    #pragma unroll
    for (int k = 0; k < 64; k++) acc = fmaf(gv[k], fc1W[k * 64 + j], acc);
    acc = fmaxf(acc, 0.0f) * fc2W[j];
    #pragma unroll
    for (int off = 16; off; off >>= 1) acc += __shfl_xor_sync(0xffffffffu, acc, off);
    if ((j & 31) == 0) partial[j >> 5] = acc;
    __syncthreads();
    if (j == 0) out[g] = partial[0] + partial[1] + fc2b[0];
}

// ---------------- launch ----------------
extern "C" void kernel_launch(void* const* d_in, const int* in_sizes, int n_in,
                              void* d_out, int out_size)
{
    const float* x     = (const float*)d_in[0];
    const float* embW  = (const float*)d_in[1];
    const float* embB  = (const float*)d_in[2];
    const float* gatW  = (const float*)d_in[3];
    const float* attS  = (const float*)d_in[4];
    const float* attD  = (const float*)d_in[5];
    const float* gatB  = (const float*)d_in[6];
    const float* bnG   = (const float*)d_in[7];
    const float* bnB   = (const float*)d_in[8];
    const float* fc1W  = (const float*)d_in[9];
    const float* fc1b  = (const float*)d_in[10];
    const float* fc2W  = (const float*)d_in[11];
    const float* fc2b  = (const float*)d_in[12];
    const int*   ei    = (const int*)d_in[13];
    const int*   batch = (const int*)d_in[14];
    float* out = (float*)d_out;

    void* p;
    cudaGetSymbolAddress(&p, d_h);  float* h   = (float*)p;
    cudaGetSymbolAddress(&p, d_xp); float* xp  = (float*)p;
    cudaGetSymbolAddress(&p, d_as); float* pas = (float*)p;
    cudaGetSymbolAddress(&p, d_ad); float* pad = (float*)p;

    const int TB = 256;
    const int gridN  = (NN + TB - 1) / TB;
    const int gridE  = (EE + TB - 1) / TB;

    // CSR by dst
    hist_kernel<<<gridE, TB>>>(ei);
    scanA_kernel<<<SCAN_BLK, 1024>>>();
    scanB_kernel<<<1, 32>>>();
    scanC_kernel<<<gridN, TB>>>();
    scatter_kernel<<<(EE + NN + TB - 1) / TB, TB>>>(ei);

    // node embedding
    gemm_kernel<128, 16, true, false, false><<<(NN + 15) / 16, 256>>>(
        x, embW, embB, nullptr, nullptr, h, nullptr, nullptr, NN);

    // layer 0 (no BN on input)
    gemm_kernel<64, 32, false, true, false><<<(NN + 31) / 32, 256>>>(
        h, gatW, nullptr, attS, attD, xp, pas, pad, NN);
    gather_kernel<<<(NN + 7) / 8, 256>>>(gatB);
    bnfin_kernel<<<1, 64>>>(bnG, bnB);

    // layers 1..3 (BN+ELU of prev layer fused into GEMM X-load)
    for (int l = 1; l < NLAYERS; l++) {
        gemm_kernel<64, 32, false, true, true><<<(NN + 31) / 32, 256>>>(
            h, gatW + l * 64 * 64, nullptr, attS + l * 64, attD + l * 64,
            xp, pas, pad, NN);
        gather_kernel<<<(NN + 7) / 8, 256>>>(gatB + l * 64);
        bnfin_kernel<<<1, 64>>>(bnG + l * 64, bnB + l * 64);
    }

    // pool (applies layer-3 BN+ELU) + head
    zero_g_kernel<<<(GG * 64 + TB - 1) / TB, TB>>>();
    pool_kernel<<<(((NN + 15) / 16) * 64 + TB - 1) / TB, TB>>>(batch);
    head_kernel<<<GG, 64>>>(fc1W, fc1b, fc2W, fc2b, out);
}

// round 7
// speedup vs baseline: 1.5209x; 1.2609x over previous
#include <cuda_runtime.h>
#include <math.h>

#define NN 50000
#define EE 800000
#define GG 256
#define NLAYERS 4
#define ETOT (EE + NN)
#define SCAN_BLK ((NN + 1023) / 1024)   // 49

// ---------------- static device scratch ----------------
__device__ __align__(16) float d_h [NN * 64];
__device__ __align__(16) float d_xp[NN * 64];
__device__ __align__(16) float d_as[NN * 4];
__device__ __align__(16) float d_ad[NN * 4];
__device__ int   d_cnt[NN];          // kept zeroed between calls
__device__ int   d_rowptr[NN + 1];
__device__ int   d_cursor[NN];
__device__ int   d_bsum[SCAN_BLK];
__device__ int   d_csrc[ETOT];
__device__ float d_bn[128];          // kept zeroed between calls
__device__ float d_bnscale[64];
__device__ float d_bnshift[64];
__device__ float d_g [GG * 64];
__device__ unsigned int d_tick;      // last-block ticket (kept zeroed)

__device__ __forceinline__ float lrelu(float x) { return x > 0.0f ? x : 0.2f * x; }
__device__ __forceinline__ float elu(float x)   { return x > 0.0f ? x : expm1f(x); }

// ---------------- CSR build ----------------
__global__ void hist_kernel(const int* __restrict__ ei) {
    int i = blockIdx.x * blockDim.x + threadIdx.x;
    if (i < EE) atomicAdd(&d_cnt[__ldg(&ei[EE + i])], 1);
}

// block-local exclusive scan (1024/block), +1 per node for self loop
__global__ void scanA_kernel() {
    __shared__ int wsum[32];
    int i = blockIdx.x * 1024 + threadIdx.x;
    int lane = threadIdx.x & 31, warp = threadIdx.x >> 5;
    int v = (i < NN) ? d_cnt[i] + 1 : 0;
    int orig = v;
    #pragma unroll
    for (int off = 1; off < 32; off <<= 1) {
        int t = __shfl_up_sync(0xffffffffu, v, off);
        if (lane >= off) v += t;
    }
    if (lane == 31) wsum[warp] = v;
    __syncthreads();
    if (threadIdx.x < 32) {
        int w = wsum[threadIdx.x];
        #pragma unroll
        for (int off = 1; off < 32; off <<= 1) {
            int t = __shfl_up_sync(0xffffffffu, w, off);
            if (lane >= off) w += t;
        }
        wsum[threadIdx.x] = w;
    }
    __syncthreads();
    int prefix = warp ? wsum[warp - 1] : 0;
    int incl = v + prefix;
    if (i < NN) d_rowptr[i] = incl - orig;
    if (threadIdx.x == 1023) d_bsum[blockIdx.x] = incl;
}

// fused: block-prefix sum (inline), cursor copy, cnt reset, zero d_g, rowptr[NN]
__global__ void scanC_kernel() {
    int i = blockIdx.x * blockDim.x + threadIdx.x;
    if (i < NN) {
        int blk = i >> 10;
        int prefix = 0;
        for (int b = 0; b < blk; b++) prefix += __ldg(&d_bsum[b]);
        int r = d_rowptr[i] + prefix;
        d_rowptr[i] = r;
        d_cursor[i] = r;
        d_cnt[i] = 0;
    }
    if (i == 0) d_rowptr[NN] = ETOT;
    if (i < GG * 64) d_g[i] = 0.0f;
}

__global__ void scatter_kernel(const int* __restrict__ ei) {
    int i = blockIdx.x * blockDim.x + threadIdx.x;
    if (i < EE) {
        int dst = __ldg(&ei[EE + i]);
        int pos = atomicAdd(&d_cursor[dst], 1);
        d_csrc[pos] = __ldg(&ei[i]);
    } else if (i < EE + NN) {
        int n = i - EE;
        int pos = atomicAdd(&d_cursor[n], 1);
        d_csrc[pos] = n;
    }
}

// ---------------- GEMM: X[nrows,K] @ W[K,64] (+bias) -> out ----------------
// thread = (2 consecutive output channels jp, jp+1) x U rows. W loaded as float2.
// BNF: fused BN+ELU of previous layer applied on X load.
// ATT: per-head attention logits via 8-lane shuffle reduction.
template<int K, int NB, bool BIAS, bool ATT, bool BNF>
__global__ void gemm_kernel(const float* __restrict__ X, const float* __restrict__ W,
                            const float* __restrict__ bias,
                            const float* __restrict__ attS, const float* __restrict__ attD,
                            float* __restrict__ out,
                            float* __restrict__ asOut, float* __restrict__ adOut,
                            int nrows)
{
    constexpr int U = NB / 8;
    __shared__ float Wsh[K * 64];
    __shared__ float Xsh[NB * K];
    int tid = threadIdx.x;
    for (int i = tid; i < K * 64; i += 256) Wsh[i] = W[i];
    int nb = blockIdx.x * NB;
    for (int i = tid; i < NB * K; i += 256) {
        int r = i / K, k = i - r * K;
        int row = nb + r;
        float v = (row < nrows) ? __ldg(&X[row * K + k]) : 0.0f;
        if (BNF) v = elu(fmaf(v, d_bnscale[k], d_bnshift[k]));
        Xsh[i] = v;
    }
    __syncthreads();

    int lane = tid & 31;
    int jp   = lane * 2;       // output channel pair
    int r0   = tid >> 5;       // 0..7 (uniform within warp -> Xsh broadcast)
    float acc0[U], acc1[U];
    #pragma unroll
    for (int u = 0; u < U; u++) { acc0[u] = 0.0f; acc1[u] = 0.0f; }

    #pragma unroll 4
    for (int k = 0; k < K; k++) {
        float2 w = *reinterpret_cast<const float2*>(&Wsh[k * 64 + jp]);
        #pragma unroll
        for (int u = 0; u < U; u++) {
            float xv = Xsh[(r0 + 8 * u) * K + k];
            acc0[u] = fmaf(xv, w.x, acc0[u]);
            acc1[u] = fmaf(xv, w.y, acc1[u]);
        }
    }

    float b0 = 0.0f, b1 = 0.0f;
    if (BIAS) { b0 = __ldg(&bias[jp]); b1 = __ldg(&bias[jp + 1]); }
    float es0 = 0.0f, es1 = 0.0f, ed0 = 0.0f, ed1 = 0.0f;
    if (ATT) {
        es0 = __ldg(&attS[jp]); es1 = __ldg(&attS[jp + 1]);
        ed0 = __ldg(&attD[jp]); ed1 = __ldg(&attD[jp + 1]);
    }

    #pragma unroll
    for (int u = 0; u < U; u++) {
        int row = nb + r0 + 8 * u;
        float v0 = acc0[u] + b0, v1 = acc1[u] + b1;
        if (row < nrows)
            *reinterpret_cast<float2*>(&out[row * 64 + jp]) = make_float2(v0, v1);
        if (ATT) {
            float vs = v0 * es0 + v1 * es1;
            float vd = v0 * ed0 + v1 * ed1;
            #pragma unroll
            for (int off = 4; off; off >>= 1) {
                vs += __shfl_xor_sync(0xffffffffu, vs, off);
                vd += __shfl_xor_sync(0xffffffffu, vd, off);
            }
            if ((lane & 7) == 0 && row < nrows) {
                int head = lane >> 3;
                asOut[row * 4 + head] = vs;
                adOut[row * 4 + head] = vd;
            }
        }
    }
}

// ---------------- attention gather: one warp per dst node, bnfin fused ----------------
// lane owns channels (2l, 2l+1), head hsel = lane>>3. One exp per lane per edge.
__global__ void gather_kernel(const float* __restrict__ gb,
                              const float* __restrict__ gamma,
                              const float* __restrict__ beta)
{
    __shared__ float shsum[64], shsq[64];
    if (threadIdx.x < 64) { shsum[threadIdx.x] = 0.0f; shsq[threadIdx.x] = 0.0f; }
    __syncthreads();

    int lane = threadIdx.x & 31;
    int hsel = lane >> 3;
    int n = blockIdx.x * 8 + (threadIdx.x >> 5);
    {
        int beg = d_rowptr[n], end = d_rowptr[n + 1];
        float adh = __ldg(&d_ad[n * 4 + hsel]);

        // phase A: per-head max; lanes of a head-group (8) cover edges stride-8
        float m = -1e30f;
        for (int i = beg + (lane & 7); i < end; i += 8) {
            int s = __ldg(&d_csrc[i]);
            m = fmaxf(m, lrelu(__ldg(&d_as[s * 4 + hsel]) + adh));
        }
        #pragma unroll
        for (int off = 4; off; off >>= 1)
            m = fmaxf(m, __shfl_xor_sync(0xffffffffu, m, off));

        // phase B: every lane walks all edges; 1 exp/edge, own head only
        float ax = 0.0f, ay = 0.0f, ssum = 0.0f;
        #pragma unroll 4
        for (int i = beg; i < end; i++) {
            int s = __ldg(&d_csrc[i]);
            float a = __ldg(&d_as[s * 4 + hsel]);
            float p = __expf(lrelu(a + adh) - m);
            float2 xv = *reinterpret_cast<const float2*>(&d_xp[s * 64 + 2 * lane]);
            ssum += p;
            ax = fmaf(xv.x, p, ax);
            ay = fmaf(xv.y, p, ay);
        }
        float inv = 1.0f / (ssum + 1e-16f);
        float v0 = ax * inv + __ldg(&gb[2 * lane]);
        float v1 = ay * inv + __ldg(&gb[2 * lane + 1]);
        *reinterpret_cast<float2*>(&d_h[n * 64 + 2 * lane]) = make_float2(v0, v1);
        atomicAdd(&shsum[2 * lane],     v0); atomicAdd(&shsq[2 * lane],     v0 * v0);
        atomicAdd(&shsum[2 * lane + 1], v1); atomicAdd(&shsq[2 * lane + 1], v1 * v1);
    }
    __syncthreads();
    if (threadIdx.x < 64) {
        atomicAdd(&d_bn[threadIdx.x],      shsum[threadIdx.x]);
        atomicAdd(&d_bn[64 + threadIdx.x], shsq[threadIdx.x]);
    }

    // last-block: fold BN stats into scale/shift, reset d_bn + ticket
    __threadfence();
    __shared__ unsigned int isLast;
    if (threadIdx.x == 0)
        isLast = (atomicInc(&d_tick, 0xffffffffu) == gridDim.x - 1) ? 1u : 0u;
    __syncthreads();
    if (isLast) {
        int j = threadIdx.x;
        if (j < 64) {
            const float invN = 1.0f / (float)NN;
            float sum = atomicAdd(&d_bn[j], 0.0f);        // L2 read
            float sq  = atomicAdd(&d_bn[64 + j], 0.0f);
            float mu  = sum * invN;
            float var = sq * invN - mu * mu;
            float sc  = rsqrtf(var + 1e-5f) * __ldg(&gamma[j]);
            d_bnscale[j] = sc;
            d_bnshift[j] = __ldg(&beta[j]) - mu * sc;
            d_bn[j] = 0.0f; d_bn[64 + j] = 0.0f;
        }
        if (j == 64) d_tick = 0;
    }
}

// ---------------- pooling (applies last layer's BN+ELU) + MLP head ----------------
// thread = (node-lane, 4-channel group); 8 nodes per thread, run-length merged atomics
__global__ void pool_kernel(const int* __restrict__ batch) {
    int tid = threadIdx.x;
    int base = blockIdx.x * 128;
    int j4 = (tid & 15) * 4;
    int nlane = tid >> 4;       // 0..15
    float4 sc = *reinterpret_cast<const float4*>(&d_bnscale[j4]);
    float4 sh = *reinterpret_cast<const float4*>(&d_bnshift[j4]);
    float4 acc = make_float4(0.f, 0.f, 0.f, 0.f);
    int curb = -1;
    #pragma unroll
    for (int k = 0; k < 8; k++) {
        int n = base + nlane + 16 * k;
        if (n >= NN) break;
        int b = __ldg(&batch[n]);
        float4 hv = *reinterpret_cast<const float4*>(&d_h[n * 64 + j4]);
        float4 v;
        v.x = elu(fmaf(hv.x, sc.x, sh.x));
        v.y = elu(fmaf(hv.y, sc.y, sh.y));
        v.z = elu(fmaf(hv.z, sc.z, sh.z));
        v.w = elu(fmaf(hv.w, sc.w, sh.w));
        if (b != curb) {
            if (curb >= 0) {
                atomicAdd(&d_g[curb * 64 + j4],     acc.x);
                atomicAdd(&d_g[curb * 64 + j4 + 1], acc.y);
                atomicAdd(&d_g[curb * 64 + j4 + 2], acc.z);
                atomicAdd(&d_g[curb * 64 + j4 + 3], acc.w);
            }
            curb = b; acc = v;
        } else {
            acc.x += v.x; acc.y += v.y; acc.z += v.z; acc.w += v.w;
        }
    }
    if (curb >= 0) {
        atomicAdd(&d_g[curb * 64 + j4],     acc.x);
        atomicAdd(&d_g[curb * 64 + j4 + 1], acc.y);
        atomicAdd(&d_g[curb * 64 + j4 + 2], acc.z);
        atomicAdd(&d_g[curb * 64 + j4 + 3], acc.w);
    }
}

__global__ void head_kernel(const float* __restrict__ fc1W, const float* __restrict__ fc1b,
                            const float* __restrict__ fc2W, const float* __restrict__ fc2b,
                            float* __restrict__ out)
{
    __shared__ float gv[64];
    __shared__ float partial[2];
    int g = blockIdx.x, j = threadIdx.x;
    gv[j] = d_g[g * 64 + j];
    __syncthreads();
    float acc = __ldg(&fc1b[j]);
    #pragma unroll
    for (int k = 0; k < 64; k++) acc = fmaf(gv[k], __ldg(&fc1W[k * 64 + j]), acc);
    acc = fmaxf(acc, 0.0f) * __ldg(&fc2W[j]);
    #pragma unroll
    for (int off = 16; off; off >>= 1) acc += __shfl_xor_sync(0xffffffffu, acc, off);
    if ((j & 31) == 0) partial[j >> 5] = acc;
    __syncthreads();
    if (j == 0) out[g] = partial[0] + partial[1] + __ldg(&fc2b[0]);
}

// ---------------- launch ----------------
extern "C" void kernel_launch(void* const* d_in, const int* in_sizes, int n_in,
                              void* d_out, int out_size)
{
    const float* x     = (const float*)d_in[0];
    const float* embW  = (const float*)d_in[1];
    const float* embB  = (const float*)d_in[2];
    const float* gatW  = (const float*)d_in[3];
    const float* attS  = (const float*)d_in[4];
    const float* attD  = (const float*)d_in[5];
    const float* gatB  = (const float*)d_in[6];
    const float* bnG   = (const float*)d_in[7];
    const float* bnB   = (const float*)d_in[8];
    const float* fc1W  = (const float*)d_in[9];
    const float* fc1b  = (const float*)d_in[10];
    const float* fc2W  = (const float*)d_in[11];
    const float* fc2b  = (const float*)d_in[12];
    const int*   ei    = (const int*)d_in[13];
    const int*   batch = (const int*)d_in[14];
    float* out = (float*)d_out;

    void* p;
    cudaGetSymbolAddress(&p, d_h);  float* h   = (float*)p;
    cudaGetSymbolAddress(&p, d_xp); float* xp  = (float*)p;
    cudaGetSymbolAddress(&p, d_as); float* pas = (float*)p;
    cudaGetSymbolAddress(&p, d_ad); float* pad = (float*)p;

    const int TB = 256;

    // CSR by dst
    hist_kernel<<<(EE + TB - 1) / TB, TB>>>(ei);
    scanA_kernel<<<SCAN_BLK, 1024>>>();
    scanC_kernel<<<(NN + TB - 1) / TB, TB>>>();
    scatter_kernel<<<(EE + NN + TB - 1) / TB, TB>>>(ei);

    // node embedding
    gemm_kernel<128, 32, true, false, false><<<(NN + 31) / 32, 256>>>(
        x, embW, embB, nullptr, nullptr, h, nullptr, nullptr, NN);

    // layer 0 (no BN on input)
    gemm_kernel<64, 64, false, true, false><<<(NN + 63) / 64, 256>>>(
        h, gatW, nullptr, attS, attD, xp, pas, pad, NN);
    gather_kernel<<<NN / 8, 256>>>(gatB, bnG, bnB);

    // layers 1..3 (prev layer's BN+ELU fused into GEMM X-load)
    for (int l = 1; l < NLAYERS; l++) {
        gemm_kernel<64, 64, false, true, true><<<(NN + 63) / 64, 256>>>(
            h, gatW + l * 64 * 64, nullptr, attS + l * 64, attD + l * 64,
            xp, pas, pad, NN);
        gather_kernel<<<NN / 8, 256>>>(gatB + l * 64, bnG + l * 64, bnB + l * 64);
    }

    // pool (applies layer-3 BN+ELU) + head
    pool_kernel<<<(NN + 127) / 128, 256>>>(batch);
    head_kernel<<<GG, 64>>>(fc1W, fc1b, fc2W, fc2b, out);
}

// round 8
// speedup vs baseline: 1.7006x; 1.1181x over previous
#include <cuda_runtime.h>
#include <math.h>

#define NN 50000
#define EE 800000
#define GG 256
#define NLAYERS 4
#define ETOT (EE + NN)
#define SCAN_BLK ((NN + 1023) / 1024)   // 49

// ---------------- static device scratch ----------------
__device__ __align__(16) float d_h [NN * 64];
__device__ __align__(16) float d_xp[NN * 64];
__device__ __align__(16) float d_as[NN * 4];
__device__ __align__(16) float d_ad[NN * 4];
__device__ int   d_cnt[NN];          // kept zeroed between calls
__device__ int   d_rowptr[NN + 1];
__device__ int   d_cursor[NN];
__device__ int   d_bsum[SCAN_BLK];
__device__ int   d_csrc[ETOT];
__device__ float d_bn[128];          // kept zeroed between calls
__device__ float d_bnscale[64];
__device__ float d_bnshift[64];
__device__ float d_g [GG * 64];
__device__ unsigned int d_tick;      // last-block ticket (kept zeroed)

__device__ __forceinline__ float lrelu(float x) { return x > 0.0f ? x : 0.2f * x; }
__device__ __forceinline__ float elu(float x)   { return x > 0.0f ? x : expm1f(x); }

// ---------------- CSR build ----------------
__global__ void hist_kernel(const int* __restrict__ ei) {
    int i0 = (blockIdx.x * blockDim.x + threadIdx.x) * 4;
    int d[4];
    #pragma unroll
    for (int j = 0; j < 4; j++)
        d[j] = (i0 + j < EE) ? __ldg(&ei[EE + i0 + j]) : -1;
    #pragma unroll
    for (int j = 0; j < 4; j++)
        if (d[j] >= 0) atomicAdd(&d_cnt[d[j]], 1);
}

// block-local exclusive scan (1024/block), +1 per node for self loop
__global__ void scanA_kernel() {
    __shared__ int wsum[32];
    int i = blockIdx.x * 1024 + threadIdx.x;
    int lane = threadIdx.x & 31, warp = threadIdx.x >> 5;
    int v = (i < NN) ? d_cnt[i] + 1 : 0;
    int orig = v;
    #pragma unroll
    for (int off = 1; off < 32; off <<= 1) {
        int t = __shfl_up_sync(0xffffffffu, v, off);
        if (lane >= off) v += t;
    }
    if (lane == 31) wsum[warp] = v;
    __syncthreads();
    if (threadIdx.x < 32) {
        int w = wsum[threadIdx.x];
        #pragma unroll
        for (int off = 1; off < 32; off <<= 1) {
            int t = __shfl_up_sync(0xffffffffu, w, off);
            if (lane >= off) w += t;
        }
        wsum[threadIdx.x] = w;
    }
    __syncthreads();
    int prefix = warp ? wsum[warp - 1] : 0;
    int incl = v + prefix;
    if (i < NN) d_rowptr[i] = incl - orig;
    if (threadIdx.x == 1023) d_bsum[blockIdx.x] = incl;
}

// fused: block-prefix (inline), cursor copy, cnt reset, zero d_g, rowptr[NN]
__global__ void scanC_kernel() {
    int i = blockIdx.x * blockDim.x + threadIdx.x;
    if (i < NN) {
        int blk = i >> 10;
        int prefix = 0;
        for (int b = 0; b < blk; b++) prefix += __ldg(&d_bsum[b]);
        int r = d_rowptr[i] + prefix;
        d_rowptr[i] = r;
        d_cursor[i] = r;
        d_cnt[i] = 0;
    }
    if (i == 0) d_rowptr[NN] = ETOT;
    if (i < GG * 64) d_g[i] = 0.0f;
}

__global__ void scatter_kernel(const int* __restrict__ ei) {
    int i0 = (blockIdx.x * blockDim.x + threadIdx.x) * 4;
    int dsts[4], srcs[4];
    #pragma unroll
    for (int j = 0; j < 4; j++) {
        int k = i0 + j;
        if (k < EE)        { dsts[j] = __ldg(&ei[EE + k]); srcs[j] = __ldg(&ei[k]); }
        else if (k < ETOT) { dsts[j] = k - EE;             srcs[j] = k - EE; }
        else               { dsts[j] = -1;                 srcs[j] = 0; }
    }
    int pos[4];
    #pragma unroll
    for (int j = 0; j < 4; j++)
        if (dsts[j] >= 0) pos[j] = atomicAdd(&d_cursor[dsts[j]], 1);
    #pragma unroll
    for (int j = 0; j < 4; j++)
        if (dsts[j] >= 0) d_csrc[pos[j]] = srcs[j];
}

// ---------------- embed GEMM: X[nrows,128] @ W[128,64] + bias ----------------
// thread = 2 channels x 8 row-slots (proven config from R6)
template<int K, int NB>
__global__ void gemm2_kernel(const float* __restrict__ X, const float* __restrict__ W,
                             const float* __restrict__ bias, float* __restrict__ out,
                             int nrows)
{
    constexpr int U = NB / 8;
    __shared__ float Wsh[K * 64];
    __shared__ float Xsh[NB * K];
    int tid = threadIdx.x;
    for (int i = tid; i < K * 64; i += 256) Wsh[i] = W[i];
    int nb = blockIdx.x * NB;
    for (int i = tid; i < NB * K; i += 256) {
        int r = i / K, k = i - r * K;
        int row = nb + r;
        Xsh[i] = (row < nrows) ? __ldg(&X[row * K + k]) : 0.0f;
    }
    __syncthreads();

    int lane = tid & 31;
    int jp   = lane * 2;
    int r0   = tid >> 5;
    float acc0[U], acc1[U];
    #pragma unroll
    for (int u = 0; u < U; u++) { acc0[u] = 0.0f; acc1[u] = 0.0f; }

    #pragma unroll 4
    for (int k = 0; k < K; k++) {
        float2 w = *reinterpret_cast<const float2*>(&Wsh[k * 64 + jp]);
        #pragma unroll
        for (int u = 0; u < U; u++) {
            float xv = Xsh[(r0 + 8 * u) * K + k];
            acc0[u] = fmaf(xv, w.x, acc0[u]);
            acc1[u] = fmaf(xv, w.y, acc1[u]);
        }
    }
    float b0 = __ldg(&bias[jp]), b1 = __ldg(&bias[jp + 1]);
    #pragma unroll
    for (int u = 0; u < U; u++) {
        int row = nb + r0 + 8 * u;
        if (row < nrows)
            *reinterpret_cast<float2*>(&out[row * 64 + jp]) = make_float2(acc0[u] + b0, acc1[u] + b1);
    }
}

// ---------------- layer GEMM: h[N,64] @ W[64,64] -> xp, + attention logits ----------------
// thread = 4 channels (j4 = (tid&15)*4) x 8 row-slots (rs = tid>>4, stride 16). NB=128.
// BNF: fused BN+ELU of previous layer applied on X load.
template<int K, int NB, bool BNF>
__global__ void gemm4_kernel(const float* __restrict__ X, const float* __restrict__ W,
                             const float* __restrict__ attS, const float* __restrict__ attD,
                             float* __restrict__ out,
                             float* __restrict__ asOut, float* __restrict__ adOut,
                             int nrows)
{
    constexpr int U = NB / 16;
    __shared__ float Wsh[K * 64];
    __shared__ float Xsh[NB * K];
    int tid = threadIdx.x;
    for (int i = tid; i < K * 64; i += 256) Wsh[i] = W[i];
    int nb = blockIdx.x * NB;
    for (int i = tid; i < NB * K; i += 256) {
        int r = i / K, k = i - r * K;
        int row = nb + r;
        float v = (row < nrows) ? __ldg(&X[row * K + k]) : 0.0f;
        if (BNF) v = elu(fmaf(v, d_bnscale[k], d_bnshift[k]));
        Xsh[i] = v;
    }
    __syncthreads();

    int lane = tid & 31;
    int cs = tid & 15, rs = tid >> 4;
    int j4 = cs * 4;
    float acc[U][4];
    #pragma unroll
    for (int u = 0; u < U; u++)
        #pragma unroll
        for (int c = 0; c < 4; c++) acc[u][c] = 0.0f;

    #pragma unroll 4
    for (int k = 0; k < K; k++) {
        float4 w = *reinterpret_cast<const float4*>(&Wsh[k * 64 + j4]);
        #pragma unroll
        for (int u = 0; u < U; u++) {
            float xv = Xsh[(rs + 16 * u) * K + k];
            acc[u][0] = fmaf(xv, w.x, acc[u][0]);
            acc[u][1] = fmaf(xv, w.y, acc[u][1]);
            acc[u][2] = fmaf(xv, w.z, acc[u][2]);
            acc[u][3] = fmaf(xv, w.w, acc[u][3]);
        }
    }

    float4 es = *reinterpret_cast<const float4*>(&attS[j4]);
    float4 ed = *reinterpret_cast<const float4*>(&attD[j4]);
    int head = cs >> 2;

    #pragma unroll
    for (int u = 0; u < U; u++) {
        int row = nb + rs + 16 * u;
        float4 v = make_float4(acc[u][0], acc[u][1], acc[u][2], acc[u][3]);
        if (row < nrows)
            *reinterpret_cast<float4*>(&out[row * 64 + j4]) = v;
        float vs = v.x * es.x + v.y * es.y + v.z * es.z + v.w * es.w;
        float vd = v.x * ed.x + v.y * ed.y + v.z * ed.z + v.w * ed.w;
        vs += __shfl_xor_sync(0xffffffffu, vs, 1);
        vd += __shfl_xor_sync(0xffffffffu, vd, 1);
        vs += __shfl_xor_sync(0xffffffffu, vs, 2);
        vd += __shfl_xor_sync(0xffffffffu, vd, 2);
        if ((lane & 3) == 0 && row < nrows) {
            asOut[row * 4 + head] = vs;
            adOut[row * 4 + head] = vd;
        }
    }
}

// ---------------- attention gather: warp/node, 2 edges in flight, bnfin fused ----------------
// half = lane>>4 picks edge parity; within half, lane covers 4 channels j4=4*(lane&15),
// head h = (lane&15)>>2. One exp per lane per owned edge.
__global__ void gather_kernel(const float* __restrict__ gb,
                              const float* __restrict__ gamma,
                              const float* __restrict__ beta)
{
    __shared__ float shsum[64], shsq[64];
    if (threadIdx.x < 64) { shsum[threadIdx.x] = 0.0f; shsq[threadIdx.x] = 0.0f; }
    __syncthreads();

    int lane = threadIdx.x & 31;
    int half = lane >> 4;
    int l15  = lane & 15;
    int h    = l15 >> 2;
    int q    = lane & 3;
    int n = blockIdx.x * 8 + (threadIdx.x >> 5);
    {
        int beg = d_rowptr[n], end = d_rowptr[n + 1];
        float adh = __ldg(&d_ad[n * 4 + h]);

        // phase A: per-head max; 8 lanes per head (q + 4*half) cover edges stride-8
        float m = -1e30f;
        for (int i = beg + q + 4 * half; i < end; i += 8) {
            int s = __ldg(&d_csrc[i]);
            m = fmaxf(m, lrelu(__ldg(&d_as[s * 4 + h]) + adh));
        }
        m = fmaxf(m, __shfl_xor_sync(0xffffffffu, m, 1));
        m = fmaxf(m, __shfl_xor_sync(0xffffffffu, m, 2));
        m = fmaxf(m, __shfl_xor_sync(0xffffffffu, m, 16));

        // phase B: half-warp owns alternate edges; float4 xp per lane
        float ax = 0.0f, ay = 0.0f, az = 0.0f, aw = 0.0f, ssum = 0.0f;
        #pragma unroll 2
        for (int i = beg + half; i < end; i += 2) {
            int s = __ldg(&d_csrc[i]);
            float a = __ldg(&d_as[s * 4 + h]);
            float4 xv = *reinterpret_cast<const float4*>(&d_xp[s * 64 + 4 * l15]);
            float p = __expf(lrelu(a + adh) - m);
            ssum += p;
            ax = fmaf(xv.x, p, ax);
            ay = fmaf(xv.y, p, ay);
            az = fmaf(xv.z, p, az);
            aw = fmaf(xv.w, p, aw);
        }
        // combine halves
        ssum += __shfl_xor_sync(0xffffffffu, ssum, 16);
        ax   += __shfl_xor_sync(0xffffffffu, ax, 16);
        ay   += __shfl_xor_sync(0xffffffffu, ay, 16);
        az   += __shfl_xor_sync(0xffffffffu, az, 16);
        aw   += __shfl_xor_sync(0xffffffffu, aw, 16);

        if (half == 0) {
            float inv = 1.0f / (ssum + 1e-16f);
            float4 gbv = *reinterpret_cast<const float4*>(&gb[4 * l15]);
            float v0 = ax * inv + gbv.x;
            float v1 = ay * inv + gbv.y;
            float v2 = az * inv + gbv.z;
            float v3 = aw * inv + gbv.w;
            *reinterpret_cast<float4*>(&d_h[n * 64 + 4 * l15]) = make_float4(v0, v1, v2, v3);
            int c = 4 * l15;
            atomicAdd(&shsum[c],     v0); atomicAdd(&shsq[c],     v0 * v0);
            atomicAdd(&shsum[c + 1], v1); atomicAdd(&shsq[c + 1], v1 * v1);
            atomicAdd(&shsum[c + 2], v2); atomicAdd(&shsq[c + 2], v2 * v2);
            atomicAdd(&shsum[c + 3], v3); atomicAdd(&shsq[c + 3], v3 * v3);
        }
    }
    __syncthreads();
    if (threadIdx.x < 64) {
        atomicAdd(&d_bn[threadIdx.x],      shsum[threadIdx.x]);
        atomicAdd(&d_bn[64 + threadIdx.x], shsq[threadIdx.x]);
    }

    // last-block: fold BN stats into scale/shift, reset d_bn + ticket
    __threadfence();
    __shared__ unsigned int isLast;
    if (threadIdx.x == 0)
        isLast = (atomicInc(&d_tick, 0xffffffffu) == gridDim.x - 1) ? 1u : 0u;
    __syncthreads();
    if (isLast) {
        int j = threadIdx.x;
        if (j < 64) {
            const float invN = 1.0f / (float)NN;
            float sum = atomicAdd(&d_bn[j], 0.0f);
            float sq  = atomicAdd(&d_bn[64 + j], 0.0f);
            float mu  = sum * invN;
            float var = sq * invN - mu * mu;
            float sc  = rsqrtf(var + 1e-5f) * __ldg(&gamma[j]);
            d_bnscale[j] = sc;
            d_bnshift[j] = __ldg(&beta[j]) - mu * sc;
            d_bn[j] = 0.0f; d_bn[64 + j] = 0.0f;
        }
        if (j == 64) d_tick = 0;
    }
}

// ---------------- pooling (applies last layer's BN+ELU) + MLP head ----------------
__global__ void pool_kernel(const int* __restrict__ batch) {
    int tid = threadIdx.x;
    int base = blockIdx.x * 128;
    int j4 = (tid & 15) * 4;
    int nlane = tid >> 4;
    float4 sc = *reinterpret_cast<const float4*>(&d_bnscale[j4]);
    float4 sh = *reinterpret_cast<const float4*>(&d_bnshift[j4]);
    float4 acc = make_float4(0.f, 0.f, 0.f, 0.f);
    int curb = -1;
    #pragma unroll
    for (int k = 0; k < 8; k++) {
        int n = base + nlane + 16 * k;
        if (n >= NN) break;
        int b = __ldg(&batch[n]);
        float4 hv = *reinterpret_cast<const float4*>(&d_h[n * 64 + j4]);
        float4 v;
        v.x = elu(fmaf(hv.x, sc.x, sh.x));
        v.y = elu(fmaf(hv.y, sc.y, sh.y));
        v.z = elu(fmaf(hv.z, sc.z, sh.z));
        v.w = elu(fmaf(hv.w, sc.w, sh.w));
        if (b != curb) {
            if (curb >= 0) {
                atomicAdd(&d_g[curb * 64 + j4],     acc.x);
                atomicAdd(&d_g[curb * 64 + j4 + 1], acc.y);
                atomicAdd(&d_g[curb * 64 + j4 + 2], acc.z);
                atomicAdd(&d_g[curb * 64 + j4 + 3], acc.w);
            }
            curb = b; acc = v;
        } else {
            acc.x += v.x; acc.y += v.y; acc.z += v.z; acc.w += v.w;
        }
    }
    if (curb >= 0) {
        atomicAdd(&d_g[curb * 64 + j4],     acc.x);
        atomicAdd(&d_g[curb * 64 + j4 + 1], acc.y);
        atomicAdd(&d_g[curb * 64 + j4 + 2], acc.z);
        atomicAdd(&d_g[curb * 64 + j4 + 3], acc.w);
    }
}

__global__ void head_kernel(const float* __restrict__ fc1W, const float* __restrict__ fc1b,
                            const float* __restrict__ fc2W, const float* __restrict__ fc2b,
                            float* __restrict__ out)
{
    __shared__ float gv[64];
    __shared__ float partial[2];
    int g = blockIdx.x, j = threadIdx.x;
    gv[j] = d_g[g * 64 + j];
    __syncthreads();
    float acc = __ldg(&fc1b[j]);
    #pragma unroll
    for (int k = 0; k < 64; k++) acc = fmaf(gv[k], __ldg(&fc1W[k * 64 + j]), acc);
    acc = fmaxf(acc, 0.0f) * __ldg(&fc2W[j]);
    #pragma unroll
    for (int off = 16; off; off >>= 1) acc += __shfl_xor_sync(0xffffffffu, acc, off);
    if ((j & 31) == 0) partial[j >> 5] = acc;
    __syncthreads();
    if (j == 0) out[g] = partial[0] + partial[1] + __ldg(&fc2b[0]);
}

// ---------------- launch ----------------
extern "C" void kernel_launch(void* const* d_in, const int* in_sizes, int n_in,
                              void* d_out, int out_size)
{
    const float* x     = (const float*)d_in[0];
    const float* embW  = (const float*)d_in[1];
    const float* embB  = (const float*)d_in[2];
    const float* gatW  = (const float*)d_in[3];
    const float* attS  = (const float*)d_in[4];
    const float* attD  = (const float*)d_in[5];
    const float* gatB  = (const float*)d_in[6];
    const float* bnG   = (const float*)d_in[7];
    const float* bnB   = (const float*)d_in[8];
    const float* fc1W  = (const float*)d_in[9];
    const float* fc1b  = (const float*)d_in[10];
    const float* fc2W  = (const float*)d_in[11];
    const float* fc2b  = (const float*)d_in[12];
    const int*   ei    = (const int*)d_in[13];
    const int*   batch = (const int*)d_in[14];
    float* out = (float*)d_out;

    void* p;
    cudaGetSymbolAddress(&p, d_h);  float* h   = (float*)p;
    cudaGetSymbolAddress(&p, d_xp); float* xp  = (float*)p;
    cudaGetSymbolAddress(&p, d_as); float* pas = (float*)p;
    cudaGetSymbolAddress(&p, d_ad); float* pad = (float*)p;

    const int TB = 256;

    // CSR by dst
    hist_kernel<<<(EE / 4 + TB - 1) / TB, TB>>>(ei);
    scanA_kernel<<<SCAN_BLK, 1024>>>();
    scanC_kernel<<<(NN + TB - 1) / TB, TB>>>();
    scatter_kernel<<<(ETOT / 4 + TB) / TB, TB>>>(ei);

    // node embedding
    gemm2_kernel<128, 32><<<(NN + 31) / 32, 256>>>(x, embW, embB, h, NN);

    // layer 0 (no BN on input)
    gemm4_kernel<64, 128, false><<<(NN + 127) / 128, 256>>>(
        h, gatW, attS, attD, xp, pas, pad, NN);
    gather_kernel<<<NN / 8, 256>>>(gatB, bnG, bnB);

    // layers 1..3 (prev layer's BN+ELU fused into GEMM X-load)
    for (int l = 1; l < NLAYERS; l++) {
        gemm4_kernel<64, 128, true><<<(NN + 127) / 128, 256>>>(
            h, gatW + l * 64 * 64, attS + l * 64, attD + l * 64,
            xp, pas, pad, NN);
        gather_kernel<<<NN / 8, 256>>>(gatB + l * 64, bnG + l * 64, bnB + l * 64);
    }

    // pool (applies layer-3 BN+ELU) + head
    pool_kernel<<<(NN + 127) / 128, 256>>>(batch);
    head_kernel<<<GG, 64>>>(fc1W, fc1b, fc2W, fc2b, out);
}

// round 9
// speedup vs baseline: 1.7854x; 1.0499x over previous
#include <cuda_runtime.h>
#include <math.h>

#define NN 50000
#define EE 800000
#define GG 256
#define NLAYERS 4
#define SCAN_BLK ((NN + 1023) / 1024)   // 49

// ---------------- static device scratch ----------------
__device__ __align__(16) float d_h [NN * 64];
__device__ __align__(16) float d_xp[NN * 64];
__device__ __align__(16) float d_as[NN * 4];
__device__ __align__(16) float d_ad[NN * 4];
__device__ int   d_cnt[NN];          // kept zeroed between calls
__device__ int   d_rowptr[NN + 1];
__device__ int   d_cursor[NN];
__device__ int   d_bsum[SCAN_BLK];
__device__ int   d_csrc[EE];         // real edges only; self-loops handled inline
__device__ float d_bn[128];          // kept zeroed between calls
__device__ float d_bnscale[64];
__device__ float d_bnshift[64];
__device__ float d_g [GG * 64];
__device__ unsigned int d_tick;      // last-block ticket (kept zeroed)

__device__ __forceinline__ float lrelu(float x) { return x > 0.0f ? x : 0.2f * x; }
__device__ __forceinline__ float elu(float x)   { return x > 0.0f ? x : expm1f(x); }

// ---------------- CSR build ----------------
__global__ void hist_kernel(const int* __restrict__ ei) {
    int i0 = (blockIdx.x * blockDim.x + threadIdx.x) * 2;
    int d0 = (i0     < EE) ? __ldg(&ei[EE + i0])     : -1;
    int d1 = (i0 + 1 < EE) ? __ldg(&ei[EE + i0 + 1]) : -1;
    if (d0 >= 0) atomicAdd(&d_cnt[d0], 1);
    if (d1 >= 0) atomicAdd(&d_cnt[d1], 1);
}

// block-local exclusive scan (1024/block)
__global__ void scanA_kernel() {
    __shared__ int wsum[32];
    int i = blockIdx.x * 1024 + threadIdx.x;
    int lane = threadIdx.x & 31, warp = threadIdx.x >> 5;
    int v = (i < NN) ? d_cnt[i] : 0;
    int orig = v;
    #pragma unroll
    for (int off = 1; off < 32; off <<= 1) {
        int t = __shfl_up_sync(0xffffffffu, v, off);
        if (lane >= off) v += t;
    }
    if (lane == 31) wsum[warp] = v;
    __syncthreads();
    if (threadIdx.x < 32) {
        int w = wsum[threadIdx.x];
        #pragma unroll
        for (int off = 1; off < 32; off <<= 1) {
            int t = __shfl_up_sync(0xffffffffu, w, off);
            if (lane >= off) w += t;
        }
        wsum[threadIdx.x] = w;
    }
    __syncthreads();
    int prefix = warp ? wsum[warp - 1] : 0;
    int incl = v + prefix;
    if (i < NN) d_rowptr[i] = incl - orig;
    if (threadIdx.x == 1023) d_bsum[blockIdx.x] = incl;
}

// fused: block-prefix (inline), cursor copy, cnt reset, zero d_g, rowptr[NN]
__global__ void scanC_kernel() {
    int i = blockIdx.x * blockDim.x + threadIdx.x;
    if (i < NN) {
        int blk = i >> 10;
        int prefix = 0;
        for (int b = 0; b < blk; b++) prefix += __ldg(&d_bsum[b]);
        int r = d_rowptr[i] + prefix;
        d_rowptr[i] = r;
        d_cursor[i] = r;
        d_cnt[i] = 0;
    }
    if (i == 0) d_rowptr[NN] = EE;
    if (i < GG * 64) d_g[i] = 0.0f;
}

__global__ void scatter_kernel(const int* __restrict__ ei) {
    int i0 = (blockIdx.x * blockDim.x + threadIdx.x) * 2;
    int d0 = -1, d1 = -1, s0 = 0, s1 = 0;
    if (i0 < EE)     { d0 = __ldg(&ei[EE + i0]);     s0 = __ldg(&ei[i0]); }
    if (i0 + 1 < EE) { d1 = __ldg(&ei[EE + i0 + 1]); s1 = __ldg(&ei[i0 + 1]); }
    int p0 = 0, p1 = 0;
    if (d0 >= 0) p0 = atomicAdd(&d_cursor[d0], 1);
    if (d1 >= 0) p1 = atomicAdd(&d_cursor[d1], 1);
    if (d0 >= 0) d_csrc[p0] = s0;
    if (d1 >= 0) d_csrc[p1] = s1;
}

// ---------------- embed GEMM: X[nrows,128] @ W[128,64] + bias ----------------
template<int K, int NB>
__global__ void gemm2_kernel(const float* __restrict__ X, const float* __restrict__ W,
                             const float* __restrict__ bias, float* __restrict__ out,
                             int nrows)
{
    constexpr int U = NB / 8;
    __shared__ float Wsh[K * 64];
    __shared__ float Xsh[NB * K];
    int tid = threadIdx.x;
    for (int i = tid; i < K * 64; i += 256) Wsh[i] = W[i];
    int nb = blockIdx.x * NB;
    for (int i = tid; i < NB * K; i += 256) {
        int r = i / K, k = i - r * K;
        int row = nb + r;
        Xsh[i] = (row < nrows) ? __ldg(&X[row * K + k]) : 0.0f;
    }
    __syncthreads();

    int lane = tid & 31;
    int jp   = lane * 2;
    int r0   = tid >> 5;
    float acc0[U], acc1[U];
    #pragma unroll
    for (int u = 0; u < U; u++) { acc0[u] = 0.0f; acc1[u] = 0.0f; }

    #pragma unroll 4
    for (int k = 0; k < K; k++) {
        float2 w = *reinterpret_cast<const float2*>(&Wsh[k * 64 + jp]);
        #pragma unroll
        for (int u = 0; u < U; u++) {
            float xv = Xsh[(r0 + 8 * u) * K + k];
            acc0[u] = fmaf(xv, w.x, acc0[u]);
            acc1[u] = fmaf(xv, w.y, acc1[u]);
        }
    }
    float b0 = __ldg(&bias[jp]), b1 = __ldg(&bias[jp + 1]);
    #pragma unroll
    for (int u = 0; u < U; u++) {
        int row = nb + r0 + 8 * u;
        if (row < nrows)
            *reinterpret_cast<float2*>(&out[row * 64 + jp]) = make_float2(acc0[u] + b0, acc1[u] + b1);
    }
}

// ---------------- layer GEMM: h[N,64] @ W[64,64] -> xp, + attention logits ----------------
template<int K, int NB, bool BNF>
__global__ void gemm4_kernel(const float* __restrict__ X, const float* __restrict__ W,
                             const float* __restrict__ attS, const float* __restrict__ attD,
                             float* __restrict__ out,
                             float* __restrict__ asOut, float* __restrict__ adOut,
                             int nrows)
{
    constexpr int U = NB / 16;
    __shared__ float Wsh[K * 64];
    __shared__ float Xsh[NB * K];
    int tid = threadIdx.x;
    for (int i = tid; i < K * 64; i += 256) Wsh[i] = W[i];
    int nb = blockIdx.x * NB;
    for (int i = tid; i < NB * K; i += 256) {
        int r = i / K, k = i - r * K;
        int row = nb + r;
        float v = (row < nrows) ? __ldg(&X[row * K + k]) : 0.0f;
        if (BNF) v = elu(fmaf(v, d_bnscale[k], d_bnshift[k]));
        Xsh[i] = v;
    }
    __syncthreads();

    int lane = tid & 31;
    int cs = tid & 15, rs = tid >> 4;
    int j4 = cs * 4;
    float acc[U][4];
    #pragma unroll
    for (int u = 0; u < U; u++)
        #pragma unroll
        for (int c = 0; c < 4; c++) acc[u][c] = 0.0f;

    #pragma unroll 4
    for (int k = 0; k < K; k++) {
        float4 w = *reinterpret_cast<const float4*>(&Wsh[k * 64 + j4]);
        #pragma unroll
        for (int u = 0; u < U; u++) {
            float xv = Xsh[(rs + 16 * u) * K + k];
            acc[u][0] = fmaf(xv, w.x, acc[u][0]);
            acc[u][1] = fmaf(xv, w.y, acc[u][1]);
            acc[u][2] = fmaf(xv, w.z, acc[u][2]);
            acc[u][3] = fmaf(xv, w.w, acc[u][3]);
        }
    }

    float4 es = *reinterpret_cast<const float4*>(&attS[j4]);
    float4 ed = *reinterpret_cast<const float4*>(&attD[j4]);
    int head = cs >> 2;

    #pragma unroll
    for (int u = 0; u < U; u++) {
        int row = nb + rs + 16 * u;
        float4 v = make_float4(acc[u][0], acc[u][1], acc[u][2], acc[u][3]);
        if (row < nrows)
            *reinterpret_cast<float4*>(&out[row * 64 + j4]) = v;
        float vs = v.x * es.x + v.y * es.y + v.z * es.z + v.w * es.w;
        float vd = v.x * ed.x + v.y * ed.y + v.z * ed.z + v.w * ed.w;
        vs += __shfl_xor_sync(0xffffffffu, vs, 1);
        vd += __shfl_xor_sync(0xffffffffu, vd, 1);
        vs += __shfl_xor_sync(0xffffffffu, vs, 2);
        vd += __shfl_xor_sync(0xffffffffu, vd, 2);
        if ((lane & 3) == 0 && row < nrows) {
            asOut[row * 4 + head] = vs;
            adOut[row * 4 + head] = vd;
        }
    }
}

// ---------------- attention gather: warp/node, SINGLE PASS (no max-sub), bnfin fused ----------------
// softmax without max subtraction is exact: exp(e)/sum(exp(e)); logits here are O(5),
// far below fp32 exp overflow. half = lane>>4 picks edge parity; lane covers 4 channels
// j4 = 4*(lane&15), head h = (lane&15)>>2. Self-loop seeded inline (half 0).
__global__ void gather_kernel(const float* __restrict__ gb,
                              const float* __restrict__ gamma,
                              const float* __restrict__ beta)
{
    __shared__ float shsum[64], shsq[64];
    if (threadIdx.x < 64) { shsum[threadIdx.x] = 0.0f; shsq[threadIdx.x] = 0.0f; }
    __syncthreads();

    int lane = threadIdx.x & 31;
    int half = lane >> 4;
    int l15  = lane & 15;
    int h    = l15 >> 2;
    int n = blockIdx.x * 8 + (threadIdx.x >> 5);
    {
        int beg = d_rowptr[n], end = d_rowptr[n + 1];
        float adh = __ldg(&d_ad[n * 4 + h]);

        float ax = 0.0f, ay = 0.0f, az = 0.0f, aw = 0.0f, ssum = 0.0f;
        if (half == 0) {
            // self loop: src = n
            float a = __ldg(&d_as[n * 4 + h]);
            float p = __expf(lrelu(a + adh));
            float4 xv = *reinterpret_cast<const float4*>(&d_xp[n * 64 + 4 * l15]);
            ssum = p;
            ax = xv.x * p; ay = xv.y * p; az = xv.z * p; aw = xv.w * p;
        }
        #pragma unroll 2
        for (int i = beg + half; i < end; i += 2) {
            int s = __ldg(&d_csrc[i]);
            float a = __ldg(&d_as[s * 4 + h]);
            float4 xv = *reinterpret_cast<const float4*>(&d_xp[s * 64 + 4 * l15]);
            float p = __expf(lrelu(a + adh));
            ssum += p;
            ax = fmaf(xv.x, p, ax);
            ay = fmaf(xv.y, p, ay);
            az = fmaf(xv.z, p, az);
            aw = fmaf(xv.w, p, aw);
        }
        // combine halves
        ssum += __shfl_xor_sync(0xffffffffu, ssum, 16);
        ax   += __shfl_xor_sync(0xffffffffu, ax, 16);
        ay   += __shfl_xor_sync(0xffffffffu, ay, 16);
        az   += __shfl_xor_sync(0xffffffffu, az, 16);
        aw   += __shfl_xor_sync(0xffffffffu, aw, 16);

        if (half == 0) {
            float inv = 1.0f / (ssum + 1e-16f);
            float4 gbv = *reinterpret_cast<const float4*>(&gb[4 * l15]);
            float v0 = ax * inv + gbv.x;
            float v1 = ay * inv + gbv.y;
            float v2 = az * inv + gbv.z;
            float v3 = aw * inv + gbv.w;
            *reinterpret_cast<float4*>(&d_h[n * 64 + 4 * l15]) = make_float4(v0, v1, v2, v3);
            int c = 4 * l15;
            atomicAdd(&shsum[c],     v0); atomicAdd(&shsq[c],     v0 * v0);
            atomicAdd(&shsum[c + 1], v1); atomicAdd(&shsq[c + 1], v1 * v1);
            atomicAdd(&shsum[c + 2], v2); atomicAdd(&shsq[c + 2], v2 * v2);
            atomicAdd(&shsum[c + 3], v3); atomicAdd(&shsq[c + 3], v3 * v3);
        }
    }
    __syncthreads();
    if (threadIdx.x < 64) {
        atomicAdd(&d_bn[threadIdx.x],      shsum[threadIdx.x]);
        atomicAdd(&d_bn[64 + threadIdx.x], shsq[threadIdx.x]);
    }

    // last-block: fold BN stats into scale/shift, reset d_bn + ticket
    __threadfence();
    __shared__ unsigned int isLast;
    if (threadIdx.x == 0)
        isLast = (atomicInc(&d_tick, 0xffffffffu) == gridDim.x - 1) ? 1u : 0u;
    __syncthreads();
    if (isLast) {
        int j = threadIdx.x;
        if (j < 64) {
            const float invN = 1.0f / (float)NN;
            float sum = atomicAdd(&d_bn[j], 0.0f);
            float sq  = atomicAdd(&d_bn[64 + j], 0.0f);
            float mu  = sum * invN;
            float var = sq * invN - mu * mu;
            float sc  = rsqrtf(var + 1e-5f) * __ldg(&gamma[j]);
            d_bnscale[j] = sc;
            d_bnshift[j] = __ldg(&beta[j]) - mu * sc;
            d_bn[j] = 0.0f; d_bn[64 + j] = 0.0f;
        }
        if (j == 64) d_tick = 0;
    }
}

// ---------------- pooling (applies last layer's BN+ELU) + MLP head ----------------
__global__ void pool_kernel(const int* __restrict__ batch) {
    int tid = threadIdx.x;
    int base = blockIdx.x * 128;
    int j4 = (tid & 15) * 4;
    int nlane = tid >> 4;
    float4 sc = *reinterpret_cast<const float4*>(&d_bnscale[j4]);
    float4 sh = *reinterpret_cast<const float4*>(&d_bnshift[j4]);
    float4 acc = make_float4(0.f, 0.f, 0.f, 0.f);
    int curb = -1;
    #pragma unroll
    for (int k = 0; k < 8; k++) {
        int n = base + nlane + 16 * k;
        if (n >= NN) break;
        int b = __ldg(&batch[n]);
        float4 hv = *reinterpret_cast<const float4*>(&d_h[n * 64 + j4]);
        float4 v;
        v.x = elu(fmaf(hv.x, sc.x, sh.x));
        v.y = elu(fmaf(hv.y, sc.y, sh.y));
        v.z = elu(fmaf(hv.z, sc.z, sh.z));
        v.w = elu(fmaf(hv.w, sc.w, sh.w));
        if (b != curb) {
            if (curb >= 0) {
                atomicAdd(&d_g[curb * 64 + j4],     acc.x);
                atomicAdd(&d_g[curb * 64 + j4 + 1], acc.y);
                atomicAdd(&d_g[curb * 64 + j4 + 2], acc.z);
                atomicAdd(&d_g[curb * 64 + j4 + 3], acc.w);
            }
            curb = b; acc = v;
        } else {
            acc.x += v.x; acc.y += v.y; acc.z += v.z; acc.w += v.w;
        }
    }
    if (curb >= 0) {
        atomicAdd(&d_g[curb * 64 + j4],     acc.x);
        atomicAdd(&d_g[curb * 64 + j4 + 1], acc.y);
        atomicAdd(&d_g[curb * 64 + j4 + 2], acc.z);
        atomicAdd(&d_g[curb * 64 + j4 + 3], acc.w);
    }
}

__global__ void head_kernel(const float* __restrict__ fc1W, const float* __restrict__ fc1b,
                            const float* __restrict__ fc2W, const float* __restrict__ fc2b,
                            float* __restrict__ out)
{
    __shared__ float gv[64];
    __shared__ float partial[2];
    int g = blockIdx.x, j = threadIdx.x;
    gv[j] = d_g[g * 64 + j];
    __syncthreads();
    float acc = __ldg(&fc1b[j]);
    #pragma unroll
    for (int k = 0; k < 64; k++) acc = fmaf(gv[k], __ldg(&fc1W[k * 64 + j]), acc);
    acc = fmaxf(acc, 0.0f) * __ldg(&fc2W[j]);
    #pragma unroll
    for (int off = 16; off; off >>= 1) acc += __shfl_xor_sync(0xffffffffu, acc, off);
    if ((j & 31) == 0) partial[j >> 5] = acc;
    __syncthreads();
    if (j == 0) out[g] = partial[0] + partial[1] + __ldg(&fc2b[0]);
}

// ---------------- launch ----------------
extern "C" void kernel_launch(void* const* d_in, const int* in_sizes, int n_in,
                              void* d_out, int out_size)
{
    const float* x     = (const float*)d_in[0];
    const float* embW  = (const float*)d_in[1];
    const float* embB  = (const float*)d_in[2];
    const float* gatW  = (const float*)d_in[3];
    const float* attS  = (const float*)d_in[4];
    const float* attD  = (const float*)d_in[5];
    const float* gatB  = (const float*)d_in[6];
    const float* bnG   = (const float*)d_in[7];
    const float* bnB   = (const float*)d_in[8];
    const float* fc1W  = (const float*)d_in[9];
    const float* fc1b  = (const float*)d_in[10];
    const float* fc2W  = (const float*)d_in[11];
    const float* fc2b  = (const float*)d_in[12];
    const int*   ei    = (const int*)d_in[13];
    const int*   batch = (const int*)d_in[14];
    float* out = (float*)d_out;

    void* p;
    cudaGetSymbolAddress(&p, d_h);  float* h   = (float*)p;
    cudaGetSymbolAddress(&p, d_xp); float* xp  = (float*)p;
    cudaGetSymbolAddress(&p, d_as); float* pas = (float*)p;
    cudaGetSymbolAddress(&p, d_ad); float* pad = (float*)p;

    const int TB = 256;

    // CSR by dst (real edges only)
    hist_kernel<<<(EE / 2 + TB - 1) / TB, TB>>>(ei);
    scanA_kernel<<<SCAN_BLK, 1024>>>();
    scanC_kernel<<<(NN + TB - 1) / TB, TB>>>();
    scatter_kernel<<<(EE / 2 + TB - 1) / TB, TB>>>(ei);

    // node embedding
    gemm2_kernel<128, 32><<<(NN + 31) / 32, 256>>>(x, embW, embB, h, NN);

    // layer 0 (no BN on input)
    gemm4_kernel<64, 128, false><<<(NN + 127) / 128, 256>>>(
        h, gatW, attS, attD, xp, pas, pad, NN);
    gather_kernel<<<NN / 8, 256>>>(gatB, bnG, bnB);

    // layers 1..3 (prev layer's BN+ELU fused into GEMM X-load)
    for (int l = 1; l < NLAYERS; l++) {
        gemm4_kernel<64, 128, true><<<(NN + 127) / 128, 256>>>(
            h, gatW + l * 64 * 64, attS + l * 64, attD + l * 64,
            xp, pas, pad, NN);
        gather_kernel<<<NN / 8, 256>>>(gatB + l * 64, bnG + l * 64, bnB + l * 64);
    }

    // pool (applies layer-3 BN+ELU) + head
    pool_kernel<<<(NN + 127) / 128, 256>>>(batch);
    head_kernel<<<GG, 64>>>(fc1W, fc1b, fc2W, fc2b, out);
}

// round 10
// speedup vs baseline: 1.8438x; 1.0327x over previous
#include <cuda_runtime.h>
#include <math.h>

#define NN 50000
#define EE 800000
#define GG 256
#define NLAYERS 4
#define SCAN_BLK ((NN + 1023) / 1024)   // 49

// ---------------- static device scratch ----------------
__device__ __align__(16) float d_h [NN * 64];
__device__ __align__(16) float d_xp[NN * 64];
__device__ __align__(16) float d_as[NN * 4];
__device__ __align__(16) float d_ad[NN * 4];
__device__ int   d_cnt[NN];          // kept zeroed between calls
__device__ int   d_rowptr[NN + 1];
__device__ int   d_cursor[NN];
__device__ int   d_bsum[SCAN_BLK];
__device__ int   d_csrc[EE];         // real edges only; self-loops handled inline
__device__ float d_bn[128];          // kept zeroed between calls
__device__ float d_bnscale[64];
__device__ float d_bnshift[64];
__device__ float d_g [GG * 64];
__device__ unsigned int d_tick;      // last-block ticket (kept zeroed)

__device__ __forceinline__ float lrelu(float x) { return x > 0.0f ? x : 0.2f * x; }
__device__ __forceinline__ float elu(float x)   { return x > 0.0f ? x : expm1f(x); }

// ---------------- CSR build ----------------
__global__ void hist_kernel(const int* __restrict__ ei) {
    int i0 = (blockIdx.x * blockDim.x + threadIdx.x) * 2;
    if (i0 < EE) {
        int2 dd = *reinterpret_cast<const int2*>(&ei[EE + i0]);   // EE even, i0 even -> aligned
        atomicAdd(&d_cnt[dd.x], 1);
        atomicAdd(&d_cnt[dd.y], 1);
    }
}

// block-local exclusive scan (1024/block)
__global__ void scanA_kernel() {
    __shared__ int wsum[32];
    int i = blockIdx.x * 1024 + threadIdx.x;
    int lane = threadIdx.x & 31, warp = threadIdx.x >> 5;
    int v = (i < NN) ? d_cnt[i] : 0;
    int orig = v;
    #pragma unroll
    for (int off = 1; off < 32; off <<= 1) {
        int t = __shfl_up_sync(0xffffffffu, v, off);
        if (lane >= off) v += t;
    }
    if (lane == 31) wsum[warp] = v;
    __syncthreads();
    if (threadIdx.x < 32) {
        int w = wsum[threadIdx.x];
        #pragma unroll
        for (int off = 1; off < 32; off <<= 1) {
            int t = __shfl_up_sync(0xffffffffu, w, off);
            if (lane >= off) w += t;
        }
        wsum[threadIdx.x] = w;
    }
    __syncthreads();
    int prefix = warp ? wsum[warp - 1] : 0;
    int incl = v + prefix;
    if (i < NN) d_rowptr[i] = incl - orig;
    if (threadIdx.x == 1023) d_bsum[blockIdx.x] = incl;
}

// fused: block-prefix (inline), cursor copy, cnt reset, zero d_g, rowptr[NN]
__global__ void scanC_kernel() {
    int i = blockIdx.x * blockDim.x + threadIdx.x;
    if (i < NN) {
        int blk = i >> 10;
        int prefix = 0;
        for (int b = 0; b < blk; b++) prefix += __ldg(&d_bsum[b]);
        int r = d_rowptr[i] + prefix;
        d_rowptr[i] = r;
        d_cursor[i] = r;
        d_cnt[i] = 0;
    }
    if (i == 0) d_rowptr[NN] = EE;
    if (i < GG * 64) d_g[i] = 0.0f;
}

__global__ void scatter_kernel(const int* __restrict__ ei) {
    int i0 = (blockIdx.x * blockDim.x + threadIdx.x) * 2;
    if (i0 < EE) {
        int2 dd = *reinterpret_cast<const int2*>(&ei[EE + i0]);
        int2 ss = *reinterpret_cast<const int2*>(&ei[i0]);
        int p0 = atomicAdd(&d_cursor[dd.x], 1);
        int p1 = atomicAdd(&d_cursor[dd.y], 1);
        d_csrc[p0] = ss.x;
        d_csrc[p1] = ss.y;
    }
}

// ---------------- embed GEMM: X[nrows,128] @ W[128,64] + bias ----------------
template<int K, int NB>
__global__ void gemm2_kernel(const float* __restrict__ X, const float* __restrict__ W,
                             const float* __restrict__ bias, float* __restrict__ out,
                             int nrows)
{
    constexpr int U = NB / 8;
    __shared__ float Wsh[K * 64];
    __shared__ float Xsh[NB * K];
    int tid = threadIdx.x;
    for (int i = tid; i < K * 64; i += 256) Wsh[i] = W[i];
    int nb = blockIdx.x * NB;
    for (int i = tid; i < NB * K; i += 256) {
        int r = i / K, k = i - r * K;
        int row = nb + r;
        Xsh[i] = (row < nrows) ? __ldg(&X[row * K + k]) : 0.0f;
    }
    __syncthreads();

    int lane = tid & 31;
    int jp   = lane * 2;
    int r0   = tid >> 5;
    float acc0[U], acc1[U];
    #pragma unroll
    for (int u = 0; u < U; u++) { acc0[u] = 0.0f; acc1[u] = 0.0f; }

    #pragma unroll 4
    for (int k = 0; k < K; k++) {
        float2 w = *reinterpret_cast<const float2*>(&Wsh[k * 64 + jp]);
        #pragma unroll
        for (int u = 0; u < U; u++) {
            float xv = Xsh[(r0 + 8 * u) * K + k];
            acc0[u] = fmaf(xv, w.x, acc0[u]);
            acc1[u] = fmaf(xv, w.y, acc1[u]);
        }
    }
    float b0 = __ldg(&bias[jp]), b1 = __ldg(&bias[jp + 1]);
    #pragma unroll
    for (int u = 0; u < U; u++) {
        int row = nb + r0 + 8 * u;
        if (row < nrows)
            *reinterpret_cast<float2*>(&out[row * 64 + jp]) = make_float2(acc0[u] + b0, acc1[u] + b1);
    }
}

// ---------------- layer GEMM: h[N,64] @ W[64,64] -> xp, + attention logits ----------------
template<int K, int NB, bool BNF>
__global__ void gemm4_kernel(const float* __restrict__ X, const float* __restrict__ W,
                             const float* __restrict__ attS, const float* __restrict__ attD,
                             float* __restrict__ out,
                             float* __restrict__ asOut, float* __restrict__ adOut,
                             int nrows)
{
    constexpr int U = NB / 16;
    __shared__ float Wsh[K * 64];
    __shared__ float Xsh[NB * K];
    int tid = threadIdx.x;
    for (int i = tid; i < K * 64; i += 256) Wsh[i] = W[i];
    int nb = blockIdx.x * NB;
    for (int i = tid; i < NB * K; i += 256) {
        int r = i / K, k = i - r * K;
        int row = nb + r;
        float v = (row < nrows) ? __ldg(&X[row * K + k]) : 0.0f;
        if (BNF) v = elu(fmaf(v, d_bnscale[k], d_bnshift[k]));
        Xsh[i] = v;
    }
    __syncthreads();

    int lane = tid & 31;
    int cs = tid & 15, rs = tid >> 4;
    int j4 = cs * 4;
    float acc[U][4];
    #pragma unroll
    for (int u = 0; u < U; u++)
        #pragma unroll
        for (int c = 0; c < 4; c++) acc[u][c] = 0.0f;

    #pragma unroll 4
    for (int k = 0; k < K; k++) {
        float4 w = *reinterpret_cast<const float4*>(&Wsh[k * 64 + j4]);
        #pragma unroll
        for (int u = 0; u < U; u++) {
            float xv = Xsh[(rs + 16 * u) * K + k];
            acc[u][0] = fmaf(xv, w.x, acc[u][0]);
            acc[u][1] = fmaf(xv, w.y, acc[u][1]);
            acc[u][2] = fmaf(xv, w.z, acc[u][2]);
            acc[u][3] = fmaf(xv, w.w, acc[u][3]);
        }
    }

    float4 es = *reinterpret_cast<const float4*>(&attS[j4]);
    float4 ed = *reinterpret_cast<const float4*>(&attD[j4]);
    int head = cs >> 2;

    #pragma unroll
    for (int u = 0; u < U; u++) {
        int row = nb + rs + 16 * u;
        float4 v = make_float4(acc[u][0], acc[u][1], acc[u][2], acc[u][3]);
        if (row < nrows)
            *reinterpret_cast<float4*>(&out[row * 64 + j4]) = v;
        float vs = v.x * es.x + v.y * es.y + v.z * es.z + v.w * es.w;
        float vd = v.x * ed.x + v.y * ed.y + v.z * ed.z + v.w * ed.w;
        vs += __shfl_xor_sync(0xffffffffu, vs, 1);
        vd += __shfl_xor_sync(0xffffffffu, vd, 1);
        vs += __shfl_xor_sync(0xffffffffu, vs, 2);
        vd += __shfl_xor_sync(0xffffffffu, vd, 2);
        if ((lane & 3) == 0 && row < nrows) {
            asOut[row * 4 + head] = vs;
            adOut[row * 4 + head] = vd;
        }
    }
}

// ---------------- attention gather: warp/node, single pass, bnfin fused ----------------
__global__ void gather_kernel(const float* __restrict__ gb,
                              const float* __restrict__ gamma,
                              const float* __restrict__ beta)
{
    __shared__ float shsum[64], shsq[64];
    if (threadIdx.x < 64) { shsum[threadIdx.x] = 0.0f; shsq[threadIdx.x] = 0.0f; }
    __syncthreads();

    int lane = threadIdx.x & 31;
    int half = lane >> 4;
    int l15  = lane & 15;
    int h    = l15 >> 2;
    int n = blockIdx.x * 8 + (threadIdx.x >> 5);
    {
        int beg = d_rowptr[n], end = d_rowptr[n + 1];
        float adh = __ldg(&d_ad[n * 4 + h]);

        float ax = 0.0f, ay = 0.0f, az = 0.0f, aw = 0.0f, ssum = 0.0f;
        if (half == 0) {
            // self loop: src = n
            float a = __ldg(&d_as[n * 4 + h]);
            float p = __expf(lrelu(a + adh));
            float4 xv = *reinterpret_cast<const float4*>(&d_xp[n * 64 + 4 * l15]);
            ssum = p;
            ax = xv.x * p; ay = xv.y * p; az = xv.z * p; aw = xv.w * p;
        }
        #pragma unroll 2
        for (int i = beg + half; i < end; i += 2) {
            int s = __ldg(&d_csrc[i]);
            float a = __ldg(&d_as[s * 4 + h]);
            float4 xv = *reinterpret_cast<const float4*>(&d_xp[s * 64 + 4 * l15]);
            float p = __expf(lrelu(a + adh));
            ssum += p;
            ax = fmaf(xv.x, p, ax);
            ay = fmaf(xv.y, p, ay);
            az = fmaf(xv.z, p, az);
            aw = fmaf(xv.w, p, aw);
        }
        // combine halves
        ssum += __shfl_xor_sync(0xffffffffu, ssum, 16);
        ax   += __shfl_xor_sync(0xffffffffu, ax, 16);
        ay   += __shfl_xor_sync(0xffffffffu, ay, 16);
        az   += __shfl_xor_sync(0xffffffffu, az, 16);
        aw   += __shfl_xor_sync(0xffffffffu, aw, 16);

        if (half == 0) {
            float inv = 1.0f / (ssum + 1e-16f);
            float4 gbv = *reinterpret_cast<const float4*>(&gb[4 * l15]);
            float v0 = ax * inv + gbv.x;
            float v1 = ay * inv + gbv.y;
            float v2 = az * inv + gbv.z;
            float v3 = aw * inv + gbv.w;
            *reinterpret_cast<float4*>(&d_h[n * 64 + 4 * l15]) = make_float4(v0, v1, v2, v3);
            int c = 4 * l15;
            atomicAdd(&shsum[c],     v0); atomicAdd(&shsq[c],     v0 * v0);
            atomicAdd(&shsum[c + 1], v1); atomicAdd(&shsq[c + 1], v1 * v1);
            atomicAdd(&shsum[c + 2], v2); atomicAdd(&shsq[c + 2], v2 * v2);
            atomicAdd(&shsum[c + 3], v3); atomicAdd(&shsq[c + 3], v3 * v3);
        }
    }
    __syncthreads();
    if (threadIdx.x < 64) {
        atomicAdd(&d_bn[threadIdx.x],      shsum[threadIdx.x]);
        atomicAdd(&d_bn[64 + threadIdx.x], shsq[threadIdx.x]);
    }

    // last-block: fold BN stats into scale/shift, reset d_bn + ticket
    __threadfence();
    __shared__ unsigned int isLast;
    if (threadIdx.x == 0)
        isLast = (atomicInc(&d_tick, 0xffffffffu) == gridDim.x - 1) ? 1u : 0u;
    __syncthreads();
    if (isLast) {
        int j = threadIdx.x;
        if (j < 64) {
            const float invN = 1.0f / (float)NN;
            float sum = atomicAdd(&d_bn[j], 0.0f);
            float sq  = atomicAdd(&d_bn[64 + j], 0.0f);
            float mu  = sum * invN;
            float var = sq * invN - mu * mu;
            float sc  = rsqrtf(var + 1e-5f) * __ldg(&gamma[j]);
            d_bnscale[j] = sc;
            d_bnshift[j] = __ldg(&beta[j]) - mu * sc;
            d_bn[j] = 0.0f; d_bn[64 + j] = 0.0f;
        }
        if (j == 64) d_tick = 0;
    }
}

// ---------------- pooling (applies last layer's BN+ELU) + MLP head ----------------
__global__ void pool_kernel(const int* __restrict__ batch) {
    int tid = threadIdx.x;
    int base = blockIdx.x * 128;
    int j4 = (tid & 15) * 4;
    int nlane = tid >> 4;
    float4 sc = *reinterpret_cast<const float4*>(&d_bnscale[j4]);
    float4 sh = *reinterpret_cast<const float4*>(&d_bnshift[j4]);
    float4 acc = make_float4(0.f, 0.f, 0.f, 0.f);
    int curb = -1;
    #pragma unroll
    for (int k = 0; k < 8; k++) {
        int n = base + nlane + 16 * k;
        if (n >= NN) break;
        int b = __ldg(&batch[n]);
        float4 hv = *reinterpret_cast<const float4*>(&d_h[n * 64 + j4]);
        float4 v;
        v.x = elu(fmaf(hv.x, sc.x, sh.x));
        v.y = elu(fmaf(hv.y, sc.y, sh.y));
        v.z = elu(fmaf(hv.z, sc.z, sh.z));
        v.w = elu(fmaf(hv.w, sc.w, sh.w));
        if (b != curb) {
            if (curb >= 0) {
                atomicAdd(&d_g[curb * 64 + j4],     acc.x);
                atomicAdd(&d_g[curb * 64 + j4 + 1], acc.y);
                atomicAdd(&d_g[curb * 64 + j4 + 2], acc.z);
                atomicAdd(&d_g[curb * 64 + j4 + 3], acc.w);
            }
            curb = b; acc = v;
        } else {
            acc.x += v.x; acc.y += v.y; acc.z += v.z; acc.w += v.w;
        }
    }
    if (curb >= 0) {
        atomicAdd(&d_g[curb * 64 + j4],     acc.x);
        atomicAdd(&d_g[curb * 64 + j4 + 1], acc.y);
        atomicAdd(&d_g[curb * 64 + j4 + 2], acc.z);
        atomicAdd(&d_g[curb * 64 + j4 + 3], acc.w);
    }
}

__global__ void head_kernel(const float* __restrict__ fc1W, const float* __restrict__ fc1b,
                            const float* __restrict__ fc2W, const float* __restrict__ fc2b,
                            float* __restrict__ out)
{
    __shared__ float gv[64];
    __shared__ float partial[2];
    int g = blockIdx.x, j = threadIdx.x;
    gv[j] = d_g[g * 64 + j];
    __syncthreads();
    float acc = __ldg(&fc1b[j]);
    #pragma unroll
    for (int k = 0; k < 64; k++) acc = fmaf(gv[k], __ldg(&fc1W[k * 64 + j]), acc);
    acc = fmaxf(acc, 0.0f) * __ldg(&fc2W[j]);
    #pragma unroll
    for (int off = 16; off; off >>= 1) acc += __shfl_xor_sync(0xffffffffu, acc, off);
    if ((j & 31) == 0) partial[j >> 5] = acc;
    __syncthreads();
    if (j == 0) out[g] = partial[0] + partial[1] + __ldg(&fc2b[0]);
}

// ---------------- launch ----------------
extern "C" void kernel_launch(void* const* d_in, const int* in_sizes, int n_in,
                              void* d_out, int out_size)
{
    const float* x     = (const float*)d_in[0];
    const float* embW  = (const float*)d_in[1];
    const float* embB  = (const float*)d_in[2];
    const float* gatW  = (const float*)d_in[3];
    const float* attS  = (const float*)d_in[4];
    const float* attD  = (const float*)d_in[5];
    const float* gatB  = (const float*)d_in[6];
    const float* bnG   = (const float*)d_in[7];
    const float* bnB   = (const float*)d_in[8];
    const float* fc1W  = (const float*)d_in[9];
    const float* fc1b  = (const float*)d_in[10];
    const float* fc2W  = (const float*)d_in[11];
    const float* fc2b  = (const float*)d_in[12];
    const int*   ei    = (const int*)d_in[13];
    const int*   batch = (const int*)d_in[14];
    float* out = (float*)d_out;

    void* p;
    cudaGetSymbolAddress(&p, d_h);  float* h   = (float*)p;
    cudaGetSymbolAddress(&p, d_xp); float* xp  = (float*)p;
    cudaGetSymbolAddress(&p, d_as); float* pas = (float*)p;
    cudaGetSymbolAddress(&p, d_ad); float* pad = (float*)p;

    // side stream + fork/join events (created once, on the uncaptured correctness
    // call; graph topology is identical on every capture — work stays deterministic)
    static cudaStream_t s2 = nullptr;
    static cudaEvent_t evFork = nullptr, evJoin = nullptr;
    if (s2 == nullptr) {
        cudaStreamCreateWithFlags(&s2, cudaStreamNonBlocking);
        cudaEventCreateWithFlags(&evFork, cudaEventDisableTiming);
        cudaEventCreateWithFlags(&evJoin, cudaEventDisableTiming);
    }

    const int TB = 256;

    // fork: branch A (s2) builds CSR while branch B (legacy) runs the GEMMs
    cudaEventRecord(evFork, 0);
    cudaStreamWaitEvent(s2, evFork, 0);

    // --- branch A: CSR by dst (real edges only) ---
    hist_kernel<<<(EE / 2 + TB - 1) / TB, TB, 0, s2>>>(ei);
    scanA_kernel<<<SCAN_BLK, 1024, 0, s2>>>();
    scanC_kernel<<<(NN + TB - 1) / TB, TB, 0, s2>>>();
    scatter_kernel<<<(EE / 2 + TB - 1) / TB, TB, 0, s2>>>(ei);
    cudaEventRecord(evJoin, s2);

    // --- branch B: node embedding + layer-0 transform ---
    gemm2_kernel<128, 32><<<(NN + 31) / 32, 256>>>(x, embW, embB, h, NN);
    gemm4_kernel<64, 128, false><<<(NN + 127) / 128, 256>>>(
        h, gatW, attS, attD, xp, pas, pad, NN);

    // join: gather needs CSR + xp/as/ad
    cudaStreamWaitEvent(0, evJoin, 0);

    gather_kernel<<<NN / 8, 256>>>(gatB, bnG, bnB);

    // layers 1..3 (prev layer's BN+ELU fused into GEMM X-load)
    for (int l = 1; l < NLAYERS; l++) {
        gemm4_kernel<64, 128, true><<<(NN + 127) / 128, 256>>>(
            h, gatW + l * 64 * 64, attS + l * 64, attD + l * 64,
            xp, pas, pad, NN);
        gather_kernel<<<NN / 8, 256>>>(gatB + l * 64, bnG + l * 64, bnB + l * 64);
    }

    // pool (applies layer-3 BN+ELU) + head
    pool_kernel<<<(NN + 127) / 128, 256>>>(batch);
    head_kernel<<<GG, 64>>>(fc1W, fc1b, fc2W, fc2b, out);
}